// round 8
// baseline (speedup 1.0000x reference)
#include <cuda_runtime.h>
#include <cuda_bf16.h>
#include <math.h>
#include <stdint.h>

#define Bb 8
#define Cc 256
#define Nn 4096
#define HEADS 4
#define HD 64
#define TSIZE (Bb*Cc*Nn)          // 8,388,608 elems per tensor
#define CTXSZ (Bb*HEADS*HD*HD)    // 131,072 per branch
#define NCHUNK 8

#define BK 16
#define WS_STRIDE 24              // 16 k + 8 pad (bf16) -> 48B rows
#define BS_STRIDE 136             // 128 n + 8 pad (bf16) -> 272B rows
#define CS_STRIDE 72              // 64 d + 8 pad (bf16) -> 144B rows
#define KS_STRIDE 40              // 32 n + 8 pad (bf16) -> 80B rows

// Scratch (device globals: no allocation allowed in kernel_launch).
__device__ float          g_q[2][TSIZE];        // fp32 conv out (softmax input)
__device__ float          g_k[2][TSIZE];
__device__ __nv_bfloat16  g_qh[2][TSIZE];       // softmaxed q (bf16)
__device__ __nv_bfloat16  g_kh[2][TSIZE];       // softmaxed k (bf16)
__device__ __nv_bfloat16  g_vh[2][TSIZE];       // v conv out (bf16)
__device__ float          g_attn[2][TSIZE];     // attention out (fp32, proj input)
__device__ float          g_ctx_part[NCHUNK * 2 * CTXSZ];  // [chunk][bh2][d][e]
__device__ __nv_bfloat16  g_ctxT[2 * CTXSZ];    // [bh2][e][d]
__device__ float          g_mean[2 * Cc];
__device__ float          g_rstd[2 * Cc];

__inline__ __device__ float warpMax(float v) {
    #pragma unroll
    for (int o = 16; o; o >>= 1) v = fmaxf(v, __shfl_xor_sync(0xffffffffu, v, o));
    return v;
}
__inline__ __device__ float warpSum(float v) {
    #pragma unroll
    for (int o = 16; o; o >>= 1) v += __shfl_xor_sync(0xffffffffu, v, o);
    return v;
}

// ---------------------------------------------------------------------------
// MMA helpers
// ---------------------------------------------------------------------------
__device__ __forceinline__ uint32_t sm_u32(const void* p) {
    return (uint32_t)__cvta_generic_to_shared(p);
}
__device__ __forceinline__ void ldsm_x4(uint32_t* r, uint32_t a) {
    asm volatile("ldmatrix.sync.aligned.m8n8.x4.shared.b16 {%0,%1,%2,%3}, [%4];"
        : "=r"(r[0]), "=r"(r[1]), "=r"(r[2]), "=r"(r[3]) : "r"(a));
}
__device__ __forceinline__ void ldsm_x4_t(uint32_t* r, uint32_t a) {
    asm volatile("ldmatrix.sync.aligned.m8n8.x4.trans.shared.b16 {%0,%1,%2,%3}, [%4];"
        : "=r"(r[0]), "=r"(r[1]), "=r"(r[2]), "=r"(r[3]) : "r"(a));
}
__device__ __forceinline__ void mma_bf16(float* c, const uint32_t* a, const uint32_t* b) {
    asm volatile("mma.sync.aligned.m16n8k16.row.col.f32.bf16.bf16.f32 "
        "{%0,%1,%2,%3}, {%4,%5,%6,%7}, {%8,%9}, {%0,%1,%2,%3};"
        : "+f"(c[0]), "+f"(c[1]), "+f"(c[2]), "+f"(c[3])
        : "r"(a[0]), "r"(a[1]), "r"(a[2]), "r"(a[3]), "r"(b[0]), "r"(b[1]));
}

// Convert 8 fp32 -> hi/lo bf16 pairs packed as uint4 (element order preserved).
__device__ __forceinline__ void cvt8(float4 a, float4 b, uint4& h, uint4& l) {
    float f[8] = {a.x, a.y, a.z, a.w, b.x, b.y, b.z, b.w};
    uint32_t hh[4], ll[4];
    #pragma unroll
    for (int i = 0; i < 4; i++) {
        __nv_bfloat16 h0 = __float2bfloat16_rn(f[2*i]);
        __nv_bfloat16 h1 = __float2bfloat16_rn(f[2*i+1]);
        __nv_bfloat16 l0 = __float2bfloat16_rn(f[2*i]   - __bfloat162float(h0));
        __nv_bfloat16 l1 = __float2bfloat16_rn(f[2*i+1] - __bfloat162float(h1));
        __nv_bfloat162 hp; hp.x = h0; hp.y = h1;
        __nv_bfloat162 lp; lp.x = l0; lp.y = l1;
        hh[i] = *(uint32_t*)&hp;
        ll[i] = *(uint32_t*)&lp;
    }
    h = make_uint4(hh[0], hh[1], hh[2], hh[3]);
    l = make_uint4(ll[0], ll[1], ll[2], ll[3]);
}

// ---------------------------------------------------------------------------
// conv1x1 body via bf16 hi/lo split tensor-core MMA (fp32-equivalent accuracy).
// Y[b][co][n] = sum_ci W[co][ci] * X[b][ci][n] + bias[co] (+ res)
// If Ybf != nullptr, output written bf16 to Ybf instead of fp32 to Y.
// Block tile 128co x 128n, BK=16, double-buffered SMEM.
// 256 threads = 8 warps in 2(M) x 4(N); warp tile 64co x 32n.
// ---------------------------------------------------------------------------
__device__ __forceinline__
void conv_body(const float* __restrict__ W, const float* __restrict__ bias,
               const float* __restrict__ X, const float* __restrict__ res,
               float* __restrict__ Y, __nv_bfloat16* __restrict__ Ybf,
               int b, int co0, int n0)
{
    __shared__ __nv_bfloat16 Wh[2][128 * WS_STRIDE];
    __shared__ __nv_bfloat16 Wl[2][128 * WS_STRIDE];
    __shared__ __nv_bfloat16 Xh[2][BK * BS_STRIDE];
    __shared__ __nv_bfloat16 Xl[2][BK * BS_STRIDE];

    const int t    = threadIdx.x;
    const int wid  = t >> 5;
    const int lane = t & 31;

    const int wco = t >> 1;          // 0..127
    const int wk  = (t & 1) * 8;     // 0 or 8
    const int xk  = t >> 4;          // 0..15
    const int xn  = (t & 15) * 8;    // 0..120

    const float* Wr = W + (size_t)(co0 + wco) * Cc + wk;
    const float* Xr = X + ((size_t)b * Cc + xk) * Nn + n0 + xn;

    const int wm = wid >> 2, wn = wid & 3;
    const int co_w = wm * 64;
    const int n_w  = wn * 32;

    const int lrow = (lane < 16) ? lane : lane - 16;
    const int lho  = (lane < 16) ? 0 : 8;

    float acc[4][4][4];
    #pragma unroll
    for (int mf = 0; mf < 4; mf++)
        #pragma unroll
        for (int nf = 0; nf < 4; nf++)
            #pragma unroll
            for (int r = 0; r < 4; r++) acc[mf][nf][r] = 0.f;

    {
        uint4 h, l;
        cvt8(*(const float4*)&Wr[0], *(const float4*)&Wr[4], h, l);
        *(uint4*)&Wh[0][wco * WS_STRIDE + wk] = h;
        *(uint4*)&Wl[0][wco * WS_STRIDE + wk] = l;
        cvt8(*(const float4*)&Xr[0], *(const float4*)&Xr[4], h, l);
        *(uint4*)&Xh[0][xk * BS_STRIDE + xn] = h;
        *(uint4*)&Xl[0][xk * BS_STRIDE + xn] = l;
    }
    __syncthreads();

    int buf = 0;
    for (int k0 = BK; k0 <= Cc; k0 += BK) {
        const bool more = (k0 < Cc);
        float4 wv0, wv1, xv0, xv1;
        if (more) {
            wv0 = *(const float4*)&Wr[k0];
            wv1 = *(const float4*)&Wr[k0 + 4];
            xv0 = *(const float4*)&Xr[(size_t)k0 * Nn];
            xv1 = *(const float4*)&Xr[(size_t)k0 * Nn + 4];
        }

        {
            uint32_t Ah[4][4], Bh[4][2], Bl[4][2];
            #pragma unroll
            for (int mf = 0; mf < 4; mf++) {
                uint32_t a = sm_u32(&Wh[buf][(co_w + 16 * mf + lrow) * WS_STRIDE + lho]);
                ldsm_x4(Ah[mf], a);
            }
            #pragma unroll
            for (int ng = 0; ng < 2; ng++) {
                uint32_t r[4];
                uint32_t a = sm_u32(&Xh[buf][lrow * BS_STRIDE + n_w + 16 * ng + lho]);
                ldsm_x4_t(r, a);
                Bh[2*ng][0] = r[0]; Bh[2*ng][1] = r[1];
                Bh[2*ng+1][0] = r[2]; Bh[2*ng+1][1] = r[3];
                uint32_t al = sm_u32(&Xl[buf][lrow * BS_STRIDE + n_w + 16 * ng + lho]);
                ldsm_x4_t(r, al);
                Bl[2*ng][0] = r[0]; Bl[2*ng][1] = r[1];
                Bl[2*ng+1][0] = r[2]; Bl[2*ng+1][1] = r[3];
            }
            #pragma unroll
            for (int mf = 0; mf < 4; mf++)
                #pragma unroll
                for (int nf = 0; nf < 4; nf++) {
                    mma_bf16(acc[mf][nf], Ah[mf], Bh[nf]);
                    mma_bf16(acc[mf][nf], Ah[mf], Bl[nf]);
                }
            #pragma unroll
            for (int mf = 0; mf < 4; mf++) {
                uint32_t Al[4];
                uint32_t a = sm_u32(&Wl[buf][(co_w + 16 * mf + lrow) * WS_STRIDE + lho]);
                ldsm_x4(Al, a);
                #pragma unroll
                for (int nf = 0; nf < 4; nf++)
                    mma_bf16(acc[mf][nf], Al, Bh[nf]);
            }
        }

        if (more) {
            const int nb = buf ^ 1;
            uint4 h, l;
            cvt8(wv0, wv1, h, l);
            *(uint4*)&Wh[nb][wco * WS_STRIDE + wk] = h;
            *(uint4*)&Wl[nb][wco * WS_STRIDE + wk] = l;
            cvt8(xv0, xv1, h, l);
            *(uint4*)&Xh[nb][xk * BS_STRIDE + xn] = h;
            *(uint4*)&Xl[nb][xk * BS_STRIDE + xn] = l;
            __syncthreads();
            buf = nb;
        }
    }

    // ---- epilogue: D frag (c0,c1)=(g,2c..2c+1), (c2,c3)=(g+8,2c..2c+1) ----
    const int g = lane >> 2;
    const int c2c = (lane & 3) * 2;
    #pragma unroll
    for (int mf = 0; mf < 4; mf++) {
        const int row0 = co0 + co_w + 16 * mf + g;
        const float bv0 = bias[row0];
        const float bv1 = bias[row0 + 8];
        #pragma unroll
        for (int nf = 0; nf < 4; nf++) {
            const int col = n0 + n_w + 8 * nf + c2c;
            const size_t off0 = ((size_t)b * Cc + row0) * Nn + col;
            const size_t off1 = off0 + (size_t)8 * Nn;
            float2 v0 = make_float2(acc[mf][nf][0] + bv0, acc[mf][nf][1] + bv0);
            float2 v1 = make_float2(acc[mf][nf][2] + bv1, acc[mf][nf][3] + bv1);
            if (Ybf) {
                __nv_bfloat162 p0; p0.x = __float2bfloat16_rn(v0.x); p0.y = __float2bfloat16_rn(v0.y);
                __nv_bfloat162 p1; p1.x = __float2bfloat16_rn(v1.x); p1.y = __float2bfloat16_rn(v1.y);
                *(__nv_bfloat162*)&Ybf[off0] = p0;
                *(__nv_bfloat162*)&Ybf[off1] = p1;
            } else {
                if (res) {
                    float2 r0 = *(const float2*)&res[off0];
                    float2 r1 = *(const float2*)&res[off1];
                    v0.x += r0.x; v0.y += r0.y;
                    v1.x += r1.x; v1.y += r1.y;
                }
                *(float2*)&Y[off0] = v0;
                *(float2*)&Y[off1] = v1;
            }
        }
    }
}

// Batched convs. grid = (Nn/128, Cc/128, 8*nConv); z -> conv id = z>>3, b = z&7.
struct ConvBatch {
    const float* W[6];
    const float* bias[6];
    const float* X[6];
    const float* res[6];
    float* Y[6];
    __nv_bfloat16* Ybf[6];
};

__global__ __launch_bounds__(256)
void conv_batch_k(ConvBatch cb)
{
    const int z   = blockIdx.z;
    const int cid = z >> 3;
    const int b   = z & 7;
    conv_body(cb.W[cid], cb.bias[cid], cb.X[cid], cb.res[cid], cb.Y[cid], cb.Ybf[cid],
              b, blockIdx.y * 128, blockIdx.x * 128);
}

// ---------------------------------------------------------------------------
// Row softmax over N=4096: reads fp32, writes bf16. grid = (B*C, 4).
// y: 0=q0, 1=k0, 2=q1, 3=k1.
// ---------------------------------------------------------------------------
struct SmPtrs { const float* src[4]; __nv_bfloat16* dst[4]; };

__global__ __launch_bounds__(256)
void softmax4_k(SmPtrs sp)
{
    const float* p = sp.src[blockIdx.y] + (size_t)blockIdx.x * Nn;
    __nv_bfloat16* o = sp.dst[blockIdx.y] + (size_t)blockIdx.x * Nn;
    const int t = threadIdx.x;
    float v[16];
    float m = -3.0e38f;
    #pragma unroll
    for (int i = 0; i < 16; i++) { v[i] = p[t + i * 256]; m = fmaxf(m, v[i]); }

    __shared__ float red[8];
    m = warpMax(m);
    if ((t & 31) == 0) red[t >> 5] = m;
    __syncthreads();
    m = red[0];
    #pragma unroll
    for (int i = 1; i < 8; i++) m = fmaxf(m, red[i]);
    __syncthreads();

    float s = 0.f;
    #pragma unroll
    for (int i = 0; i < 16; i++) { v[i] = __expf(v[i] - m); s += v[i]; }
    s = warpSum(s);
    if ((t & 31) == 0) red[t >> 5] = s;
    __syncthreads();
    s = red[0];
    #pragma unroll
    for (int i = 1; i < 8; i++) s += red[i];

    const float inv = 1.f / s;
    #pragma unroll
    for (int i = 0; i < 16; i++) o[t + i * 256] = __float2bfloat16_rn(v[i] * inv);
}

// ---------------------------------------------------------------------------
// ctx partials via MMA: part[chunk][bh2][d][e] = sum_{n in chunk} K[d,n]*V[e,n]
// A = K tile [d][n] row-major (k=n contig) -> non-trans ldmatrix (W pattern).
// B = V tile [e][n] (e = mma n-dim, k=n contig) = canonical col-major
//     -> non-trans ldmatrix, lane map row=(lane&7)+((lane>>4)<<3), koff=lane&8.
// Tile 32 n per iter, register-prefetched single SMEM buffer.
// grid = (NCHUNK, 64); 256 threads; warps 4(M=d16) x 2(N=e32).
// ---------------------------------------------------------------------------
__global__ __launch_bounds__(256)
void ctx_part_k()
{
    const int chunk = blockIdx.x;
    const int bh2 = blockIdx.y;
    const int branch = bh2 >> 5;
    const int bh = bh2 & 31;
    const int b = bh >> 2, h = bh & 3;

    __shared__ __nv_bfloat16 Ks[64 * KS_STRIDE];
    __shared__ __nv_bfloat16 Vs[64 * KS_STRIDE];

    const int t    = threadIdx.x;
    const int wid  = t >> 5;
    const int lane = t & 31;

    const int wm = wid >> 1;         // 0..3 -> d offset wm*16
    const int wn = wid & 1;          // 0..1 -> e offset wn*32

    // A lane map (non-trans, rows 0-15 then k-half)
    const int lrow = (lane < 16) ? lane : lane - 16;
    const int lho  = (lane < 16) ? 0 : 8;
    // B lane map (non-trans col-major: m0=e0-7/k0-7, m1=e0-7/k8-15, m2=e8-15/k0-7, m3=e8-15/k8-15)
    const int brow = (lane & 7) + ((lane >> 4) << 3);
    const int bko  = lane & 8;

    const __nv_bfloat16* Kp = g_kh[branch] + ((size_t)b * Cc + h * HD) * Nn;
    const __nv_bfloat16* Vp = g_vh[branch] + ((size_t)b * Cc + h * HD) * Nn;

    float acc[4][4];
    #pragma unroll
    for (int nf = 0; nf < 4; nf++)
        #pragma unroll
        for (int r = 0; r < 4; r++) acc[nf][r] = 0.f;

    // staging map: one uint4 (8 bf16) per thread; 4 threads cover 64B of a row
    const int srow = t >> 2;          // 0..63
    const int scol = (t & 3) * 8;     // 0, 8, 16, 24
    const int nBeg = chunk * (Nn / NCHUNK);
    const int NIT = (Nn / NCHUNK) / 32;   // 16 iterations

    uint4 kreg = *(const uint4*)&Kp[(size_t)srow * Nn + nBeg + scol];
    uint4 vreg = *(const uint4*)&Vp[(size_t)srow * Nn + nBeg + scol];

    for (int it = 0; it < NIT; it++) {
        __syncthreads();     // all MMA reads of previous tile complete
        *(uint4*)&Ks[srow * KS_STRIDE + scol] = kreg;
        *(uint4*)&Vs[srow * KS_STRIDE + scol] = vreg;
        if (it + 1 < NIT) {
            const int n1 = nBeg + (it + 1) * 32;
            kreg = *(const uint4*)&Kp[(size_t)srow * Nn + n1 + scol];
            vreg = *(const uint4*)&Vp[(size_t)srow * Nn + n1 + scol];
        }
        __syncthreads();

        #pragma unroll
        for (int kk = 0; kk < 2; kk++) {
            uint32_t A[4];
            ldsm_x4(A, sm_u32(&Ks[(wm * 16 + lrow) * KS_STRIDE + kk * 16 + lho]));
            uint32_t Bf[4][2];
            #pragma unroll
            for (int eg = 0; eg < 2; eg++) {
                uint32_t r[4];
                ldsm_x4(r, sm_u32(&Vs[(wn * 32 + eg * 16 + brow) * KS_STRIDE + kk * 16 + bko]));
                Bf[2*eg][0]   = r[0]; Bf[2*eg][1]   = r[1];
                Bf[2*eg+1][0] = r[2]; Bf[2*eg+1][1] = r[3];
            }
            #pragma unroll
            for (int nf = 0; nf < 4; nf++)
                mma_bf16(acc[nf], A, Bf[nf]);
        }
    }

    // D frag: rows d = wm*16+g (+8), cols e = wn*32 + nf*8 + 2*(lane&3)
    float* outp = g_ctx_part + ((size_t)chunk * 64 + bh2) * (HD * HD);
    const int g = lane >> 2;
    const int cc = (lane & 3) * 2;
    #pragma unroll
    for (int nf = 0; nf < 4; nf++) {
        const int e = wn * 32 + nf * 8 + cc;
        const int d0 = wm * 16 + g;
        *(float2*)&outp[d0 * HD + e]       = make_float2(acc[nf][0], acc[nf][1]);
        *(float2*)&outp[(d0 + 8) * HD + e] = make_float2(acc[nf][2], acc[nf][3]);
    }
}

// Reduce chunks; write transposed bf16 ctxT[bh2][e][d].
__global__ __launch_bounds__(256)
void ctx_reduce_k()
{
    const int idx = blockIdx.x * 256 + threadIdx.x;
    if (idx < 2 * CTXSZ) {
        const int bh2 = idx >> 12;
        const int r = idx & 4095;
        const int e = r >> 6;
        const int d = r & 63;
        float s = 0.f;
        #pragma unroll
        for (int c = 0; c < NCHUNK; c++)
            s += g_ctx_part[((size_t)c * 64 + bh2) * (HD * HD) + d * HD + e];
        g_ctxT[idx] = __float2bfloat16_rn(s);   // idx = bh2*4096 + e*64 + d
    }
}

// ---------------------------------------------------------------------------
// attn out via MMA: out[e][n] = sum_d ctxT[e][d] * q[d][n]
// A = ctxT [e][d] row-major -> non-trans (W pattern). B = q [d][n] -> trans (X pattern).
// grid = (Nn/128, 64); 256 threads; warps 2(M=e32) x 4(N=n32); K=64 (4 iters).
// ---------------------------------------------------------------------------
__global__ __launch_bounds__(256)
void attn_out_k()
{
    const int n0 = blockIdx.x * 128;
    const int bh2 = blockIdx.y;
    const int branch = bh2 >> 5;
    const int bh = bh2 & 31;
    const int b = bh >> 2, h = bh & 3;

    __shared__ __nv_bfloat16 Cs[64 * CS_STRIDE];   // ctxT rows e, cols d
    __shared__ __nv_bfloat16 Qs[64 * BS_STRIDE];   // q rows d, cols n (128)

    const int t    = threadIdx.x;
    const int wid  = t >> 5;
    const int lane = t & 31;

    // stage ctxT (64x64) : 4096 bf16 -> 2 uint4 per thread
    {
        const __nv_bfloat16* src = g_ctxT + (size_t)bh2 * (HD * HD);
        #pragma unroll
        for (int i = 0; i < 2; i++) {
            const int idx = t + i * 256;
            const int row = idx >> 3;
            const int c8 = (idx & 7) * 8;
            *(uint4*)&Cs[row * CS_STRIDE + c8] = *(const uint4*)&src[row * HD + c8];
        }
    }
    // stage q tile (64 x 128): 8192 bf16 -> 4 uint4 per thread
    {
        const __nv_bfloat16* src = g_qh[branch] + ((size_t)b * Cc + h * HD) * Nn + n0;
        #pragma unroll
        for (int i = 0; i < 4; i++) {
            const int idx = t + i * 256;
            const int row = idx >> 4;
            const int c8 = (idx & 15) * 8;
            *(uint4*)&Qs[row * BS_STRIDE + c8] = *(const uint4*)&src[(size_t)row * Nn + c8];
        }
    }
    __syncthreads();

    const int wm = wid >> 2;         // 0..1 -> e offset wm*32
    const int wn = wid & 3;          // 0..3 -> n offset wn*32
    const int lrow = (lane < 16) ? lane : lane - 16;
    const int lho  = (lane < 16) ? 0 : 8;

    float acc[2][4][4];
    #pragma unroll
    for (int mf = 0; mf < 2; mf++)
        #pragma unroll
        for (int nf = 0; nf < 4; nf++)
            #pragma unroll
            for (int r = 0; r < 4; r++) acc[mf][nf][r] = 0.f;

    #pragma unroll
    for (int kk = 0; kk < 4; kk++) {
        uint32_t A[2][4], Bf[4][2];
        #pragma unroll
        for (int mf = 0; mf < 2; mf++)
            ldsm_x4(A[mf], sm_u32(&Cs[(wm * 32 + mf * 16 + lrow) * CS_STRIDE + kk * 16 + lho]));
        #pragma unroll
        for (int ng = 0; ng < 2; ng++) {
            uint32_t r[4];
            ldsm_x4_t(r, sm_u32(&Qs[(kk * 16 + lrow) * BS_STRIDE + wn * 32 + 16 * ng + lho]));
            Bf[2*ng][0]   = r[0]; Bf[2*ng][1]   = r[1];
            Bf[2*ng+1][0] = r[2]; Bf[2*ng+1][1] = r[3];
        }
        #pragma unroll
        for (int mf = 0; mf < 2; mf++)
            #pragma unroll
            for (int nf = 0; nf < 4; nf++)
                mma_bf16(acc[mf][nf], A[mf], Bf[nf]);
    }

    const int g = lane >> 2;
    const int cc = (lane & 3) * 2;
    float* outp = g_attn[branch] + ((size_t)b * Cc + h * HD) * Nn;
    #pragma unroll
    for (int mf = 0; mf < 2; mf++) {
        const int e0 = wm * 32 + mf * 16 + g;
        #pragma unroll
        for (int nf = 0; nf < 4; nf++) {
            const int col = n0 + wn * 32 + nf * 8 + cc;
            *(float2*)&outp[(size_t)e0 * Nn + col]       = make_float2(acc[mf][nf][0], acc[mf][nf][1]);
            *(float2*)&outp[(size_t)(e0 + 8) * Nn + col] = make_float2(acc[mf][nf][2], acc[mf][nf][3]);
        }
    }
}

// ---------------------------------------------------------------------------
// BatchNorm stats per channel, both branches. grid = 512 (branch*256 + c).
// ---------------------------------------------------------------------------
__global__ __launch_bounds__(256)
void bn_stats_k(const float* __restrict__ out)
{
    const int branch = blockIdx.x >> 8;
    const int c = blockIdx.x & 255;
    const float* Y = out + (size_t)branch * TSIZE;
    const int t = threadIdx.x;
    float s1 = 0.f, s2 = 0.f;
    for (int b = 0; b < Bb; b++) {
        const float* p = Y + ((size_t)b * Cc + c) * Nn;
        for (int i = t; i < Nn; i += 256) {
            float x = p[i];
            s1 += x;
            s2 = fmaf(x, x, s2);
        }
    }
    __shared__ float r1[8], r2[8];
    s1 = warpSum(s1); s2 = warpSum(s2);
    if ((t & 31) == 0) { r1[t >> 5] = s1; r2[t >> 5] = s2; }
    __syncthreads();
    if (t == 0) {
        float a = 0.f, q = 0.f;
        #pragma unroll
        for (int i = 0; i < 8; i++) { a += r1[i]; q += r2[i]; }
        const float mean = a * (1.f / 32768.f);
        const float var  = q * (1.f / 32768.f) - mean * mean;
        g_mean[branch * Cc + c] = mean;
        g_rstd[branch * Cc + c] = rsqrtf(var + 1e-5f);
    }
}

__global__ __launch_bounds__(256)
void bn_apply_k(float* __restrict__ Y, const float* __restrict__ gamma,
                const float* __restrict__ beta)
{
    const size_t idx4 = (size_t)blockIdx.x * 256 + threadIdx.x;
    const size_t tot4 = (size_t)2 * TSIZE / 4;
    if (idx4 >= tot4) return;
    const size_t e = idx4 * 4;
    const int branch = (int)(e / TSIZE);
    const int c = (int)((e / Nn) % Cc);
    const float m = g_mean[branch * Cc + c];
    const float r = g_rstd[branch * Cc + c];
    const float g = gamma[c] * r;
    const float bt = beta[c] - m * g;
    float4 x = ((float4*)Y)[idx4];
    x.x = fmaf(x.x, g, bt);
    x.y = fmaf(x.y, g, bt);
    x.z = fmaf(x.z, g, bt);
    x.w = fmaf(x.w, g, bt);
    ((float4*)Y)[idx4] = x;
}

// ---------------------------------------------------------------------------
extern "C" void kernel_launch(void* const* d_in, const int* in_sizes, int n_in,
                              void* d_out, int out_size)
{
    const float* rgb_low  = (const float*)d_in[0];
    const float* rgb_high = (const float*)d_in[1];
    const float* dsm_low  = (const float*)d_in[2];
    const float* dsm_high = (const float*)d_in[3];
    const float* w_q1 = (const float*)d_in[4];   const float* b_q1 = (const float*)d_in[5];
    const float* w_k1 = (const float*)d_in[6];   const float* b_k1 = (const float*)d_in[7];
    const float* w_v1 = (const float*)d_in[8];   const float* b_v1 = (const float*)d_in[9];
    const float* w_q2 = (const float*)d_in[10];  const float* b_q2 = (const float*)d_in[11];
    const float* w_k2 = (const float*)d_in[12];  const float* b_k2 = (const float*)d_in[13];
    const float* w_v2 = (const float*)d_in[14];  const float* b_v2 = (const float*)d_in[15];
    const float* w_p1 = (const float*)d_in[16];  const float* b_p1 = (const float*)d_in[17];
    const float* w_p2 = (const float*)d_in[18];  const float* b_p2 = (const float*)d_in[19];
    const float* gamma = (const float*)d_in[20];
    const float* beta  = (const float*)d_in[21];

    float* out = (float*)d_out;

    float *q32, *k32, *ap;
    __nv_bfloat16 *qh, *kh, *vh;
    cudaGetSymbolAddress((void**)&q32, g_q);
    cudaGetSymbolAddress((void**)&k32, g_k);
    cudaGetSymbolAddress((void**)&qh,  g_qh);
    cudaGetSymbolAddress((void**)&kh,  g_kh);
    cudaGetSymbolAddress((void**)&vh,  g_vh);
    cudaGetSymbolAddress((void**)&ap,  g_attn);

    // dsm passthrough (independent; enqueue first)
    cudaMemcpyAsync(out + (size_t)2 * TSIZE, dsm_low,  (size_t)TSIZE * sizeof(float),
                    cudaMemcpyDeviceToDevice);
    cudaMemcpyAsync(out + (size_t)3 * TSIZE, dsm_high, (size_t)TSIZE * sizeof(float),
                    cudaMemcpyDeviceToDevice);

    // ---- All six q/k/v convs, both branches, one launch (v -> bf16) ----
    {
        ConvBatch cb;
        cb.W[0] = w_q1; cb.bias[0] = b_q1; cb.X[0] = rgb_low;  cb.res[0] = nullptr; cb.Y[0] = q32;         cb.Ybf[0] = nullptr;
        cb.W[1] = w_k1; cb.bias[1] = b_k1; cb.X[1] = dsm_high; cb.res[1] = nullptr; cb.Y[1] = k32;         cb.Ybf[1] = nullptr;
        cb.W[2] = w_v1; cb.bias[2] = b_v1; cb.X[2] = dsm_high; cb.res[2] = nullptr; cb.Y[2] = nullptr;     cb.Ybf[2] = vh;
        cb.W[3] = w_q2; cb.bias[3] = b_q2; cb.X[3] = rgb_high; cb.res[3] = nullptr; cb.Y[3] = q32 + TSIZE; cb.Ybf[3] = nullptr;
        cb.W[4] = w_k2; cb.bias[4] = b_k2; cb.X[4] = dsm_low;  cb.res[4] = nullptr; cb.Y[4] = k32 + TSIZE; cb.Ybf[4] = nullptr;
        cb.W[5] = w_v2; cb.bias[5] = b_v2; cb.X[5] = dsm_low;  cb.res[5] = nullptr; cb.Y[5] = nullptr;     cb.Ybf[5] = vh + TSIZE;
        conv_batch_k<<<dim3(Nn / 128, Cc / 128, 6 * Bb), 256>>>(cb);
    }

    // ---- Softmax q1, k1, q2, k2 (fp32 in, bf16 out) ----
    {
        SmPtrs sp;
        sp.src[0] = q32;         sp.dst[0] = qh;
        sp.src[1] = k32;         sp.dst[1] = kh;
        sp.src[2] = q32 + TSIZE; sp.dst[2] = qh + TSIZE;
        sp.src[3] = k32 + TSIZE; sp.dst[3] = kh + TSIZE;
        softmax4_k<<<dim3(Bb * Cc, 4), 256>>>(sp);
    }

    // ---- Attention (MMA, both branches batched) ----
    ctx_part_k<<<dim3(NCHUNK, 64), 256>>>();
    ctx_reduce_k<<<(2 * CTXSZ + 255) / 256, 256>>>();
    attn_out_k<<<dim3(Nn / 128, 64), 256>>>();

    // ---- Both proj convs (with residual) in one launch ----
    {
        ConvBatch cb;
        cb.W[0] = w_p1; cb.bias[0] = b_p1; cb.X[0] = ap;         cb.res[0] = rgb_low;  cb.Y[0] = out;         cb.Ybf[0] = nullptr;
        cb.W[1] = w_p2; cb.bias[1] = b_p2; cb.X[1] = ap + TSIZE; cb.res[1] = rgb_high; cb.Y[1] = out + TSIZE; cb.Ybf[1] = nullptr;
        #pragma unroll
        for (int i = 2; i < 6; i++) {
            cb.W[i] = nullptr; cb.bias[i] = nullptr; cb.X[i] = nullptr;
            cb.res[i] = nullptr; cb.Y[i] = nullptr; cb.Ybf[i] = nullptr;
        }
        conv_batch_k<<<dim3(Nn / 128, Cc / 128, 2 * Bb), 256>>>(cb);
    }

    // ---- BatchNorm ----
    bn_stats_k<<<2 * Cc, 256>>>(out);
    bn_apply_k<<<(2 * TSIZE / 4 + 255) / 256, 256>>>(out, gamma, beta);
}

// round 13
// speedup vs baseline: 1.2914x; 1.2914x over previous
#include <cuda_runtime.h>
#include <cuda_bf16.h>
#include <math.h>
#include <stdint.h>

#define Bb 8
#define Cc 256
#define Nn 4096
#define HEADS 4
#define HD 64
#define TSIZE (Bb*Cc*Nn)          // 8,388,608 elems per tensor
#define CTXSZ (Bb*HEADS*HD*HD)    // 131,072 per branch
#define NCHUNK 8

#define BK 16
#define WS_STRIDE 24              // 16 k + 8 pad (bf16) -> 48B rows
#define BS_STRIDE 136             // 128 n + 8 pad (bf16) -> 272B rows
#define CS_STRIDE 72              // 64 d + 8 pad (bf16) -> 144B rows
#define KS_STRIDE 40              // 32 n + 8 pad (bf16) -> 80B rows

// Scratch (device globals: no allocation allowed in kernel_launch).
__device__ __nv_bfloat16  g_qh[2][TSIZE];       // q conv out, then softmaxed (in place)
__device__ __nv_bfloat16  g_kh[2][TSIZE];       // k conv out, then softmaxed (in place)
__device__ __nv_bfloat16  g_vh[2][TSIZE];       // v conv out
__device__ __nv_bfloat16  g_attnh[2][TSIZE];    // attention out (bf16, proj input)
__device__ float          g_ctx_part[NCHUNK * 2 * CTXSZ];  // [chunk][bh2][e][d] (transposed)
__device__ __nv_bfloat16  g_ctxT[2 * CTXSZ];    // [bh2][e][d]
__device__ float          g_bns1[2 * 256 * 256];  // BN partial sums   [branch][c][b*32+nt]
__device__ float          g_bns2[2 * 256 * 256];  // BN partial sumsq
__device__ float          g_mean[2 * Cc];
__device__ float          g_rstd[2 * Cc];

__inline__ __device__ float warpMax(float v) {
    #pragma unroll
    for (int o = 16; o; o >>= 1) v = fmaxf(v, __shfl_xor_sync(0xffffffffu, v, o));
    return v;
}
__inline__ __device__ float warpSum(float v) {
    #pragma unroll
    for (int o = 16; o; o >>= 1) v += __shfl_xor_sync(0xffffffffu, v, o);
    return v;
}

// ---------------------------------------------------------------------------
// MMA helpers
// ---------------------------------------------------------------------------
__device__ __forceinline__ uint32_t sm_u32(const void* p) {
    return (uint32_t)__cvta_generic_to_shared(p);
}
__device__ __forceinline__ void ldsm_x4(uint32_t* r, uint32_t a) {
    asm volatile("ldmatrix.sync.aligned.m8n8.x4.shared.b16 {%0,%1,%2,%3}, [%4];"
        : "=r"(r[0]), "=r"(r[1]), "=r"(r[2]), "=r"(r[3]) : "r"(a));
}
__device__ __forceinline__ void ldsm_x4_t(uint32_t* r, uint32_t a) {
    asm volatile("ldmatrix.sync.aligned.m8n8.x4.trans.shared.b16 {%0,%1,%2,%3}, [%4];"
        : "=r"(r[0]), "=r"(r[1]), "=r"(r[2]), "=r"(r[3]) : "r"(a));
}
__device__ __forceinline__ void mma_bf16(float* c, const uint32_t* a, const uint32_t* b) {
    asm volatile("mma.sync.aligned.m16n8k16.row.col.f32.bf16.bf16.f32 "
        "{%0,%1,%2,%3}, {%4,%5,%6,%7}, {%8,%9}, {%0,%1,%2,%3};"
        : "+f"(c[0]), "+f"(c[1]), "+f"(c[2]), "+f"(c[3])
        : "r"(a[0]), "r"(a[1]), "r"(a[2]), "r"(a[3]), "r"(b[0]), "r"(b[1]));
}

// Convert 8 fp32 -> 8 bf16 packed as uint4 (element order preserved).
__device__ __forceinline__ uint4 cvt8h(float4 a, float4 b) {
    float f[8] = {a.x, a.y, a.z, a.w, b.x, b.y, b.z, b.w};
    uint32_t hh[4];
    #pragma unroll
    for (int i = 0; i < 4; i++) {
        __nv_bfloat162 hp;
        hp.x = __float2bfloat16_rn(f[2*i]);
        hp.y = __float2bfloat16_rn(f[2*i+1]);
        hh[i] = *(uint32_t*)&hp;
    }
    return make_uint4(hh[0], hh[1], hh[2], hh[3]);
}

// ---------------------------------------------------------------------------
// conv1x1 core: single-pass bf16 tensor-core MMA.
// Y[b][co][n] = sum_ci W[co][ci] * X[b][ci][n] + bias[co] (+ res)
// XBF: input X is bf16 (else fp32, converted on stage).
// DOBN: accumulate deterministic per-block BN partials (requires fp32 Y + res).
// Block tile 128co x 128n, BK=16, double-buffered SMEM.
// 256 threads = 8 warps in 2(M) x 4(N); warp tile 64co x 32n.
// ---------------------------------------------------------------------------
template<bool XBF, bool DOBN>
__device__ __forceinline__
void conv_core(const float* __restrict__ W, const float* __restrict__ bias,
               const float* __restrict__ Xf, const __nv_bfloat16* __restrict__ Xb,
               const float* __restrict__ res,
               float* __restrict__ Y, __nv_bfloat16* __restrict__ Ybf,
               float* __restrict__ bns1, float* __restrict__ bns2,
               int b, int co0, int n0, int nt)
{
    __shared__ __nv_bfloat16 Wh[2][128 * WS_STRIDE];
    __shared__ __nv_bfloat16 Xh[2][BK * BS_STRIDE];

    const int t    = threadIdx.x;
    const int wid  = t >> 5;
    const int lane = t & 31;

    const int wco = t >> 1;          // 0..127
    const int wk  = (t & 1) * 8;     // 0 or 8
    const int xk  = t >> 4;          // 0..15
    const int xn  = (t & 15) * 8;    // 0..120

    const float* Wr = W + (size_t)(co0 + wco) * Cc + wk;
    const float*         Xrf = XBF ? nullptr : (Xf + ((size_t)b * Cc + xk) * Nn + n0 + xn);
    const __nv_bfloat16* Xrb = XBF ? (Xb + ((size_t)b * Cc + xk) * Nn + n0 + xn) : nullptr;

    const int wm = wid >> 2, wn = wid & 3;
    const int co_w = wm * 64;
    const int n_w  = wn * 32;

    const int lrow = (lane < 16) ? lane : lane - 16;
    const int lho  = (lane < 16) ? 0 : 8;

    float acc[4][4][4];
    #pragma unroll
    for (int mf = 0; mf < 4; mf++)
        #pragma unroll
        for (int nf = 0; nf < 4; nf++)
            #pragma unroll
            for (int r = 0; r < 4; r++) acc[mf][nf][r] = 0.f;

    // ---- stage k-tile 0 ----
    {
        *(uint4*)&Wh[0][wco * WS_STRIDE + wk] =
            cvt8h(*(const float4*)&Wr[0], *(const float4*)&Wr[4]);
        if constexpr (XBF) {
            *(uint4*)&Xh[0][xk * BS_STRIDE + xn] = *(const uint4*)&Xrb[0];
        } else {
            *(uint4*)&Xh[0][xk * BS_STRIDE + xn] =
                cvt8h(*(const float4*)&Xrf[0], *(const float4*)&Xrf[4]);
        }
    }
    __syncthreads();

    int buf = 0;
    for (int k0 = BK; k0 <= Cc; k0 += BK) {
        const bool more = (k0 < Cc);
        float4 wv0, wv1, xv0, xv1;
        uint4 xvb;
        if (more) {
            wv0 = *(const float4*)&Wr[k0];
            wv1 = *(const float4*)&Wr[k0 + 4];
            if constexpr (XBF) {
                xvb = *(const uint4*)&Xrb[(size_t)k0 * Nn];
            } else {
                xv0 = *(const float4*)&Xrf[(size_t)k0 * Nn];
                xv1 = *(const float4*)&Xrf[(size_t)k0 * Nn + 4];
            }
        }

        // ---- single-pass MMA on current buffer ----
        {
            uint32_t Ah[4][4], Bh[4][2];
            #pragma unroll
            for (int mf = 0; mf < 4; mf++)
                ldsm_x4(Ah[mf], sm_u32(&Wh[buf][(co_w + 16 * mf + lrow) * WS_STRIDE + lho]));
            #pragma unroll
            for (int ng = 0; ng < 2; ng++) {
                uint32_t r[4];
                ldsm_x4_t(r, sm_u32(&Xh[buf][lrow * BS_STRIDE + n_w + 16 * ng + lho]));
                Bh[2*ng][0] = r[0]; Bh[2*ng][1] = r[1];
                Bh[2*ng+1][0] = r[2]; Bh[2*ng+1][1] = r[3];
            }
            #pragma unroll
            for (int mf = 0; mf < 4; mf++)
                #pragma unroll
                for (int nf = 0; nf < 4; nf++)
                    mma_bf16(acc[mf][nf], Ah[mf], Bh[nf]);
        }

        if (more) {
            const int nb = buf ^ 1;
            *(uint4*)&Wh[nb][wco * WS_STRIDE + wk] = cvt8h(wv0, wv1);
            if constexpr (XBF) {
                *(uint4*)&Xh[nb][xk * BS_STRIDE + xn] = xvb;
            } else {
                *(uint4*)&Xh[nb][xk * BS_STRIDE + xn] = cvt8h(xv0, xv1);
            }
            __syncthreads();
            buf = nb;
        }
    }

    // ---- epilogue: D frag (c0,c1)=(g,2c..2c+1), (c2,c3)=(g+8,2c..2c+1) ----
    const int g = lane >> 2;
    const int c2c = (lane & 3) * 2;

    float s1[4][2], s2[4][2];
    if constexpr (DOBN) {
        #pragma unroll
        for (int mf = 0; mf < 4; mf++) { s1[mf][0]=0.f; s1[mf][1]=0.f; s2[mf][0]=0.f; s2[mf][1]=0.f; }
    }

    #pragma unroll
    for (int mf = 0; mf < 4; mf++) {
        const int row0 = co0 + co_w + 16 * mf + g;
        const float bv0 = bias[row0];
        const float bv1 = bias[row0 + 8];
        #pragma unroll
        for (int nf = 0; nf < 4; nf++) {
            const int col = n0 + n_w + 8 * nf + c2c;
            const size_t off0 = ((size_t)b * Cc + row0) * Nn + col;
            const size_t off1 = off0 + (size_t)8 * Nn;
            float2 v0 = make_float2(acc[mf][nf][0] + bv0, acc[mf][nf][1] + bv0);
            float2 v1 = make_float2(acc[mf][nf][2] + bv1, acc[mf][nf][3] + bv1);
            if constexpr (DOBN) {
                float2 r0 = *(const float2*)&res[off0];
                float2 r1 = *(const float2*)&res[off1];
                v0.x += r0.x; v0.y += r0.y;
                v1.x += r1.x; v1.y += r1.y;
                *(float2*)&Y[off0] = v0;
                *(float2*)&Y[off1] = v1;
                s1[mf][0] += v0.x + v0.y;
                s2[mf][0] = fmaf(v0.x, v0.x, fmaf(v0.y, v0.y, s2[mf][0]));
                s1[mf][1] += v1.x + v1.y;
                s2[mf][1] = fmaf(v1.x, v1.x, fmaf(v1.y, v1.y, s2[mf][1]));
            } else {
                __nv_bfloat162 p0, p1;
                p0.x = __float2bfloat16_rn(v0.x); p0.y = __float2bfloat16_rn(v0.y);
                p1.x = __float2bfloat16_rn(v1.x); p1.y = __float2bfloat16_rn(v1.y);
                *(__nv_bfloat162*)&Ybf[off0] = p0;
                *(__nv_bfloat162*)&Ybf[off1] = p1;
            }
        }
    }

    if constexpr (DOBN) {
        // reduce over the 4 lanes sharing a row (lane&3 varies col)
        #pragma unroll
        for (int mf = 0; mf < 4; mf++)
            #pragma unroll
            for (int hh = 0; hh < 2; hh++) {
                s1[mf][hh] += __shfl_xor_sync(0xffffffffu, s1[mf][hh], 1);
                s1[mf][hh] += __shfl_xor_sync(0xffffffffu, s1[mf][hh], 2);
                s2[mf][hh] += __shfl_xor_sync(0xffffffffu, s2[mf][hh], 1);
                s2[mf][hh] += __shfl_xor_sync(0xffffffffu, s2[mf][hh], 2);
            }
        __shared__ float bnred[2][128][4];
        if ((lane & 3) == 0) {
            #pragma unroll
            for (int mf = 0; mf < 4; mf++)
                #pragma unroll
                for (int hh = 0; hh < 2; hh++) {
                    const int lrw = co_w + 16 * mf + g + 8 * hh;   // 0..127
                    bnred[0][lrw][wn] = s1[mf][hh];
                    bnred[1][lrw][wn] = s2[mf][hh];
                }
        }
        __syncthreads();
        if (t < 128) {
            float a = 0.f, q = 0.f;
            #pragma unroll
            for (int w = 0; w < 4; w++) { a += bnred[0][t][w]; q += bnred[1][t][w]; }
            const int slot = (co0 + t) * 256 + b * 32 + nt;
            bns1[slot] = a;
            bns2[slot] = q;
        }
    }
}

// Batched q/k/v convs (fp32 in, bf16 out). grid = (32, 2, 48); cid = z%6, b = z/6.
struct QkvBatch {
    const float* W[6];
    const float* bias[6];
    const float* X[6];
    __nv_bfloat16* Y[6];
};

__global__ __launch_bounds__(256, 2)
void conv_qkv_k(QkvBatch cb)
{
    const int z   = blockIdx.z;
    const int cid = z % 6;
    const int b   = z / 6;
    conv_core<false, false>(cb.W[cid], cb.bias[cid], cb.X[cid], nullptr, nullptr,
                            nullptr, cb.Y[cid], nullptr, nullptr,
                            b, blockIdx.y * 128, blockIdx.x * 128, blockIdx.x);
}

// Batched proj convs (bf16 in, fp32 out + residual + BN partials). grid = (32, 2, 16).
struct ProjBatch {
    const float* W[2];
    const float* bias[2];
    const __nv_bfloat16* X[2];
    const float* res[2];
    float* Y[2];
    float* s1[2];
    float* s2[2];
};

__global__ __launch_bounds__(256, 2)
void conv_proj_k(ProjBatch cb)
{
    const int z   = blockIdx.z;
    const int cid = z & 1;
    const int b   = z >> 1;
    conv_core<true, true>(cb.W[cid], cb.bias[cid], nullptr, cb.X[cid], cb.res[cid],
                          cb.Y[cid], nullptr, cb.s1[cid], cb.s2[cid],
                          b, blockIdx.y * 128, blockIdx.x * 128, blockIdx.x);
}

// ---------------------------------------------------------------------------
// Row softmax over N=4096 (bf16 in place, fp32 math), four tensors per launch.
// grid = (B*C, 4), 256 threads, uint4 vectorized (8 bf16 per load).
// ---------------------------------------------------------------------------
struct SmPtrs { __nv_bfloat16* p[4]; };

__global__ __launch_bounds__(256)
void softmax4_k(SmPtrs sp)
{
    __nv_bfloat16* p = sp.p[blockIdx.y] + (size_t)blockIdx.x * Nn;
    uint4* row4 = (uint4*)p;                  // 512 uint4 per row
    const int t = threadIdx.x;

    uint4 ua = row4[t];
    uint4 ub = row4[t + 256];
    float v[16];
    {
        const uint32_t* w = (const uint32_t*)&ua;
        #pragma unroll
        for (int i = 0; i < 4; i++) {
            __nv_bfloat162 h = *(const __nv_bfloat162*)&w[i];
            v[2*i]   = __bfloat162float(h.x);
            v[2*i+1] = __bfloat162float(h.y);
        }
        const uint32_t* w2 = (const uint32_t*)&ub;
        #pragma unroll
        for (int i = 0; i < 4; i++) {
            __nv_bfloat162 h = *(const __nv_bfloat162*)&w2[i];
            v[8+2*i]   = __bfloat162float(h.x);
            v[8+2*i+1] = __bfloat162float(h.y);
        }
    }

    float m = -3.0e38f;
    #pragma unroll
    for (int i = 0; i < 16; i++) m = fmaxf(m, v[i]);

    __shared__ float red[8];
    m = warpMax(m);
    if ((t & 31) == 0) red[t >> 5] = m;
    __syncthreads();
    m = red[0];
    #pragma unroll
    for (int i = 1; i < 8; i++) m = fmaxf(m, red[i]);
    __syncthreads();

    float s = 0.f;
    #pragma unroll
    for (int i = 0; i < 16; i++) { v[i] = __expf(v[i] - m); s += v[i]; }
    s = warpSum(s);
    if ((t & 31) == 0) red[t >> 5] = s;
    __syncthreads();
    s = red[0];
    #pragma unroll
    for (int i = 1; i < 8; i++) s += red[i];

    const float inv = 1.f / s;
    {
        uint32_t* w = (uint32_t*)&ua;
        #pragma unroll
        for (int i = 0; i < 4; i++) {
            __nv_bfloat162 h;
            h.x = __float2bfloat16_rn(v[2*i] * inv);
            h.y = __float2bfloat16_rn(v[2*i+1] * inv);
            w[i] = *(uint32_t*)&h;
        }
        uint32_t* w2 = (uint32_t*)&ub;
        #pragma unroll
        for (int i = 0; i < 4; i++) {
            __nv_bfloat162 h;
            h.x = __float2bfloat16_rn(v[8+2*i] * inv);
            h.y = __float2bfloat16_rn(v[8+2*i+1] * inv);
            w2[i] = *(uint32_t*)&h;
        }
    }
    row4[t] = ua;
    row4[t + 256] = ub;
}

// ---------------------------------------------------------------------------
// ctx partials via MMA: part[chunk][bh2][e][d] = sum_{n in chunk} K[d,n]*V[e,n]
// (stored TRANSPOSED so ctx_reduce reads coalesce)
// A = K tile [d][n] row-major -> non-trans ldmatrix (W pattern).
// B = V tile [e][n] canonical col-major -> non-trans ldmatrix,
//     lane map row=(lane&7)+((lane>>4)<<3), koff=lane&8.
// grid = (NCHUNK, 64); 256 threads; warps 4(M=d16) x 2(N=e32).
// ---------------------------------------------------------------------------
__global__ __launch_bounds__(256)
void ctx_part_k()
{
    const int chunk = blockIdx.x;
    const int bh2 = blockIdx.y;
    const int branch = bh2 >> 5;
    const int bh = bh2 & 31;
    const int b = bh >> 2, h = bh & 3;

    __shared__ __nv_bfloat16 Ks[64 * KS_STRIDE];
    __shared__ __nv_bfloat16 Vs[64 * KS_STRIDE];

    const int t    = threadIdx.x;
    const int wid  = t >> 5;
    const int lane = t & 31;

    const int wm = wid >> 1;         // 0..3 -> d offset wm*16
    const int wn = wid & 1;          // 0..1 -> e offset wn*32

    const int lrow = (lane < 16) ? lane : lane - 16;
    const int lho  = (lane < 16) ? 0 : 8;
    const int brow = (lane & 7) + ((lane >> 4) << 3);
    const int bko  = lane & 8;

    const __nv_bfloat16* Kp = g_kh[branch] + ((size_t)b * Cc + h * HD) * Nn;
    const __nv_bfloat16* Vp = g_vh[branch] + ((size_t)b * Cc + h * HD) * Nn;

    float acc[4][4];
    #pragma unroll
    for (int nf = 0; nf < 4; nf++)
        #pragma unroll
        for (int r = 0; r < 4; r++) acc[nf][r] = 0.f;

    const int srow = t >> 2;          // 0..63
    const int scol = (t & 3) * 8;     // 0, 8, 16, 24
    const int nBeg = chunk * (Nn / NCHUNK);
    const int NIT = (Nn / NCHUNK) / 32;   // 16 iterations

    uint4 kreg = *(const uint4*)&Kp[(size_t)srow * Nn + nBeg + scol];
    uint4 vreg = *(const uint4*)&Vp[(size_t)srow * Nn + nBeg + scol];

    for (int it = 0; it < NIT; it++) {
        __syncthreads();
        *(uint4*)&Ks[srow * KS_STRIDE + scol] = kreg;
        *(uint4*)&Vs[srow * KS_STRIDE + scol] = vreg;
        if (it + 1 < NIT) {
            const int n1 = nBeg + (it + 1) * 32;
            kreg = *(const uint4*)&Kp[(size_t)srow * Nn + n1 + scol];
            vreg = *(const uint4*)&Vp[(size_t)srow * Nn + n1 + scol];
        }
        __syncthreads();

        #pragma unroll
        for (int kk = 0; kk < 2; kk++) {
            uint32_t A[4];
            ldsm_x4(A, sm_u32(&Ks[(wm * 16 + lrow) * KS_STRIDE + kk * 16 + lho]));
            uint32_t Bf[4][2];
            #pragma unroll
            for (int eg = 0; eg < 2; eg++) {
                uint32_t r[4];
                ldsm_x4(r, sm_u32(&Vs[(wn * 32 + eg * 16 + brow) * KS_STRIDE + kk * 16 + bko]));
                Bf[2*eg][0]   = r[0]; Bf[2*eg][1]   = r[1];
                Bf[2*eg+1][0] = r[2]; Bf[2*eg+1][1] = r[3];
            }
            #pragma unroll
            for (int nf = 0; nf < 4; nf++)
                mma_bf16(acc[nf], A, Bf[nf]);
        }
    }

    // transposed store: part[e][d]
    float* outp = g_ctx_part + ((size_t)chunk * 64 + bh2) * (HD * HD);
    const int g = lane >> 2;
    const int cc = (lane & 3) * 2;
    #pragma unroll
    for (int nf = 0; nf < 4; nf++) {
        const int e = wn * 32 + nf * 8 + cc;
        const int d0 = wm * 16 + g;
        outp[e * HD + d0]           = acc[nf][0];
        outp[(e + 1) * HD + d0]     = acc[nf][1];
        outp[e * HD + d0 + 8]       = acc[nf][2];
        outp[(e + 1) * HD + d0 + 8] = acc[nf][3];
    }
}

// Reduce chunks; partials already transposed -> coalesced reads; bf16 out.
__global__ __launch_bounds__(256)
void ctx_reduce_k()
{
    const int idx = blockIdx.x * 256 + threadIdx.x;
    if (idx < 2 * CTXSZ) {
        const int bh2 = idx >> 12;
        const int r = idx & 4095;      // = e*64 + d
        float s = 0.f;
        #pragma unroll
        for (int c = 0; c < NCHUNK; c++)
            s += g_ctx_part[((size_t)c * 64 + bh2) * (HD * HD) + r];
        g_ctxT[idx] = __float2bfloat16_rn(s);
    }
}

// ---------------------------------------------------------------------------
// attn out via MMA: out[e][n] = sum_d ctxT[e][d] * q[d][n]  (bf16 out)
// A = ctxT [e][d] row-major -> non-trans (W pattern). B = q [d][n] -> trans (X pattern).
// grid = (Nn/128, 64); 256 threads; warps 2(M=e32) x 4(N=n32); K=64 (4 iters).
// ---------------------------------------------------------------------------
__global__ __launch_bounds__(256)
void attn_out_k()
{
    const int n0 = blockIdx.x * 128;
    const int bh2 = blockIdx.y;
    const int branch = bh2 >> 5;
    const int bh = bh2 & 31;
    const int b = bh >> 2, h = bh & 3;

    __shared__ __nv_bfloat16 Cs[64 * CS_STRIDE];   // ctxT rows e, cols d
    __shared__ __nv_bfloat16 Qs[64 * BS_STRIDE];   // q rows d, cols n (128)

    const int t    = threadIdx.x;
    const int wid  = t >> 5;
    const int lane = t & 31;

    {
        const __nv_bfloat16* src = g_ctxT + (size_t)bh2 * (HD * HD);
        #pragma unroll
        for (int i = 0; i < 2; i++) {
            const int idx = t + i * 256;
            const int row = idx >> 3;
            const int c8 = (idx & 7) * 8;
            *(uint4*)&Cs[row * CS_STRIDE + c8] = *(const uint4*)&src[row * HD + c8];
        }
    }
    {
        const __nv_bfloat16* src = g_qh[branch] + ((size_t)b * Cc + h * HD) * Nn + n0;
        #pragma unroll
        for (int i = 0; i < 4; i++) {
            const int idx = t + i * 256;
            const int row = idx >> 4;
            const int c8 = (idx & 15) * 8;
            *(uint4*)&Qs[row * BS_STRIDE + c8] = *(const uint4*)&src[(size_t)row * Nn + c8];
        }
    }
    __syncthreads();

    const int wm = wid >> 2;
    const int wn = wid & 3;
    const int lrow = (lane < 16) ? lane : lane - 16;
    const int lho  = (lane < 16) ? 0 : 8;

    float acc[2][4][4];
    #pragma unroll
    for (int mf = 0; mf < 2; mf++)
        #pragma unroll
        for (int nf = 0; nf < 4; nf++)
            #pragma unroll
            for (int r = 0; r < 4; r++) acc[mf][nf][r] = 0.f;

    #pragma unroll
    for (int kk = 0; kk < 4; kk++) {
        uint32_t A[2][4], Bf[4][2];
        #pragma unroll
        for (int mf = 0; mf < 2; mf++)
            ldsm_x4(A[mf], sm_u32(&Cs[(wm * 32 + mf * 16 + lrow) * CS_STRIDE + kk * 16 + lho]));
        #pragma unroll
        for (int ng = 0; ng < 2; ng++) {
            uint32_t r[4];
            ldsm_x4_t(r, sm_u32(&Qs[(kk * 16 + lrow) * BS_STRIDE + wn * 32 + 16 * ng + lho]));
            Bf[2*ng][0]   = r[0]; Bf[2*ng][1]   = r[1];
            Bf[2*ng+1][0] = r[2]; Bf[2*ng+1][1] = r[3];
        }
        #pragma unroll
        for (int mf = 0; mf < 2; mf++)
            #pragma unroll
            for (int nf = 0; nf < 4; nf++)
                mma_bf16(acc[mf][nf], A[mf], Bf[nf]);
    }

    const int g = lane >> 2;
    const int cc = (lane & 3) * 2;
    __nv_bfloat16* outp = g_attnh[branch] + ((size_t)b * Cc + h * HD) * Nn;
    #pragma unroll
    for (int mf = 0; mf < 2; mf++) {
        const int e0 = wm * 32 + mf * 16 + g;
        #pragma unroll
        for (int nf = 0; nf < 4; nf++) {
            const int col = n0 + wn * 32 + nf * 8 + cc;
            __nv_bfloat162 p0, p1;
            p0.x = __float2bfloat16_rn(acc[mf][nf][0]);
            p0.y = __float2bfloat16_rn(acc[mf][nf][1]);
            p1.x = __float2bfloat16_rn(acc[mf][nf][2]);
            p1.y = __float2bfloat16_rn(acc[mf][nf][3]);
            *(__nv_bfloat162*)&outp[(size_t)e0 * Nn + col]       = p0;
            *(__nv_bfloat162*)&outp[(size_t)(e0 + 8) * Nn + col] = p1;
        }
    }
}

// ---------------------------------------------------------------------------
// BN finalize from partials. grid = 512 (branch*256 + c), 256 threads.
// ---------------------------------------------------------------------------
__global__ __launch_bounds__(256)
void bn_finalize_k()
{
    const int ch = blockIdx.x;       // branch*256 + c
    const int t = threadIdx.x;
    float s1 = g_bns1[(size_t)ch * 256 + t];
    float s2 = g_bns2[(size_t)ch * 256 + t];
    __shared__ float r1[8], r2[8];
    s1 = warpSum(s1); s2 = warpSum(s2);
    if ((t & 31) == 0) { r1[t >> 5] = s1; r2[t >> 5] = s2; }
    __syncthreads();
    if (t == 0) {
        float a = 0.f, q = 0.f;
        #pragma unroll
        for (int i = 0; i < 8; i++) { a += r1[i]; q += r2[i]; }
        const float mean = a * (1.f / 32768.f);
        const float var  = q * (1.f / 32768.f) - mean * mean;
        g_mean[ch] = mean;
        g_rstd[ch] = rsqrtf(var + 1e-5f);
    }
}

__global__ __launch_bounds__(256)
void bn_apply_k(float* __restrict__ Y, const float* __restrict__ gamma,
                const float* __restrict__ beta)
{
    const size_t idx4 = (size_t)blockIdx.x * 256 + threadIdx.x;
    const size_t tot4 = (size_t)2 * TSIZE / 4;
    if (idx4 >= tot4) return;
    const size_t e = idx4 * 4;
    const int branch = (int)(e / TSIZE);
    const int c = (int)((e / Nn) % Cc);
    const float m = g_mean[branch * Cc + c];
    const float r = g_rstd[branch * Cc + c];
    const float g = gamma[c] * r;
    const float bt = beta[c] - m * g;
    float4 x = ((float4*)Y)[idx4];
    x.x = fmaf(x.x, g, bt);
    x.y = fmaf(x.y, g, bt);
    x.z = fmaf(x.z, g, bt);
    x.w = fmaf(x.w, g, bt);
    ((float4*)Y)[idx4] = x;
}

// ---------------------------------------------------------------------------
extern "C" void kernel_launch(void* const* d_in, const int* in_sizes, int n_in,
                              void* d_out, int out_size)
{
    const float* rgb_low  = (const float*)d_in[0];
    const float* rgb_high = (const float*)d_in[1];
    const float* dsm_low  = (const float*)d_in[2];
    const float* dsm_high = (const float*)d_in[3];
    const float* w_q1 = (const float*)d_in[4];   const float* b_q1 = (const float*)d_in[5];
    const float* w_k1 = (const float*)d_in[6];   const float* b_k1 = (const float*)d_in[7];
    const float* w_v1 = (const float*)d_in[8];   const float* b_v1 = (const float*)d_in[9];
    const float* w_q2 = (const float*)d_in[10];  const float* b_q2 = (const float*)d_in[11];
    const float* w_k2 = (const float*)d_in[12];  const float* b_k2 = (const float*)d_in[13];
    const float* w_v2 = (const float*)d_in[14];  const float* b_v2 = (const float*)d_in[15];
    const float* w_p1 = (const float*)d_in[16];  const float* b_p1 = (const float*)d_in[17];
    const float* w_p2 = (const float*)d_in[18];  const float* b_p2 = (const float*)d_in[19];
    const float* gamma = (const float*)d_in[20];
    const float* beta  = (const float*)d_in[21];

    float* out = (float*)d_out;

    __nv_bfloat16 *qh, *kh, *vh, *ah;
    float *bs1, *bs2;
    cudaGetSymbolAddress((void**)&qh,  g_qh);
    cudaGetSymbolAddress((void**)&kh,  g_kh);
    cudaGetSymbolAddress((void**)&vh,  g_vh);
    cudaGetSymbolAddress((void**)&ah,  g_attnh);
    cudaGetSymbolAddress((void**)&bs1, g_bns1);
    cudaGetSymbolAddress((void**)&bs2, g_bns2);

    // dsm passthrough (independent; enqueue first)
    cudaMemcpyAsync(out + (size_t)2 * TSIZE, dsm_low,  (size_t)TSIZE * sizeof(float),
                    cudaMemcpyDeviceToDevice);
    cudaMemcpyAsync(out + (size_t)3 * TSIZE, dsm_high, (size_t)TSIZE * sizeof(float),
                    cudaMemcpyDeviceToDevice);

    // ---- All six q/k/v convs (fp32 -> bf16), both branches, one launch ----
    {
        QkvBatch cb;
        cb.W[0] = w_q1; cb.bias[0] = b_q1; cb.X[0] = rgb_low;  cb.Y[0] = qh;
        cb.W[1] = w_k1; cb.bias[1] = b_k1; cb.X[1] = dsm_high; cb.Y[1] = kh;
        cb.W[2] = w_v1; cb.bias[2] = b_v1; cb.X[2] = dsm_high; cb.Y[2] = vh;
        cb.W[3] = w_q2; cb.bias[3] = b_q2; cb.X[3] = rgb_high; cb.Y[3] = qh + TSIZE;
        cb.W[4] = w_k2; cb.bias[4] = b_k2; cb.X[4] = dsm_low;  cb.Y[4] = kh + TSIZE;
        cb.W[5] = w_v2; cb.bias[5] = b_v2; cb.X[5] = dsm_low;  cb.Y[5] = vh + TSIZE;
        conv_qkv_k<<<dim3(Nn / 128, Cc / 128, 6 * Bb), 256>>>(cb);
    }

    // ---- Softmax q1, k1, q2, k2 (bf16 in place) ----
    {
        SmPtrs sp;
        sp.p[0] = qh; sp.p[1] = kh; sp.p[2] = qh + TSIZE; sp.p[3] = kh + TSIZE;
        softmax4_k<<<dim3(Bb * Cc, 4), 256>>>(sp);
    }

    // ---- Attention (MMA, both branches batched) ----
    ctx_part_k<<<dim3(NCHUNK, 64), 256>>>();
    ctx_reduce_k<<<(2 * CTXSZ + 255) / 256, 256>>>();
    attn_out_k<<<dim3(Nn / 128, 64), 256>>>();

    // ---- Both proj convs (bf16 in, fp32 out + residual + BN partials) ----
    {
        ProjBatch cb;
        cb.W[0] = w_p1; cb.bias[0] = b_p1; cb.X[0] = ah;         cb.res[0] = rgb_low;
        cb.Y[0] = out;         cb.s1[0] = bs1;         cb.s2[0] = bs2;
        cb.W[1] = w_p2; cb.bias[1] = b_p2; cb.X[1] = ah + TSIZE; cb.res[1] = rgb_high;
        cb.Y[1] = out + TSIZE; cb.s1[1] = bs1 + 65536; cb.s2[1] = bs2 + 65536;
        conv_proj_k<<<dim3(Nn / 128, Cc / 128, 2 * Bb), 256>>>(cb);
    }

    // ---- BatchNorm ----
    bn_finalize_k<<<2 * Cc, 256>>>();
    bn_apply_k<<<(2 * TSIZE / 4 + 255) / 256, 256>>>(out, gamma, beta);
}

// round 14
// speedup vs baseline: 1.3063x; 1.0115x over previous
#include <cuda_runtime.h>
#include <cuda_bf16.h>
#include <math.h>
#include <stdint.h>

#define Bb 8
#define Cc 256
#define Nn 4096
#define HEADS 4
#define HD 64
#define TSIZE (Bb*Cc*Nn)          // 8,388,608 elems per tensor
#define CTXSZ (Bb*HEADS*HD*HD)    // 131,072 per branch
#define NCHUNK 8

#define BK 16
#define WS_STRIDE 24              // 16 k + 8 pad (bf16) -> 48B rows
#define BS_STRIDE 136             // 128 n + 8 pad (bf16) -> 272B rows
#define CS_STRIDE 72              // 64 d + 8 pad (bf16) -> 144B rows
#define KS_STRIDE 40              // 32 n + 8 pad (bf16) -> 80B rows

// Scratch (device globals: no allocation allowed in kernel_launch).
__device__ __nv_bfloat16  g_qh[2][TSIZE];       // q conv out, then softmaxed (in place)
__device__ __nv_bfloat16  g_kh[2][TSIZE];       // k conv out, then softmaxed (in place)
__device__ __nv_bfloat16  g_vh[2][TSIZE];       // v conv out
__device__ __nv_bfloat16  g_attnh[2][TSIZE];    // attention out (bf16, proj input)
__device__ float          g_ctx_part[NCHUNK * 2 * CTXSZ];  // [chunk][bh2][e][d] (transposed)
__device__ __nv_bfloat16  g_ctxT[2 * CTXSZ];    // [bh2][e][d]
__device__ float          g_bns1[2 * 256 * 256];  // BN partial sums   [branch][c][b*32+nt]
__device__ float          g_bns2[2 * 256 * 256];  // BN partial sumsq
__device__ float          g_mean[2 * Cc];
__device__ float          g_rstd[2 * Cc];

__inline__ __device__ float warpMax(float v) {
    #pragma unroll
    for (int o = 16; o; o >>= 1) v = fmaxf(v, __shfl_xor_sync(0xffffffffu, v, o));
    return v;
}
__inline__ __device__ float warpSum(float v) {
    #pragma unroll
    for (int o = 16; o; o >>= 1) v += __shfl_xor_sync(0xffffffffu, v, o);
    return v;
}

// ---------------------------------------------------------------------------
// MMA helpers
// ---------------------------------------------------------------------------
__device__ __forceinline__ uint32_t sm_u32(const void* p) {
    return (uint32_t)__cvta_generic_to_shared(p);
}
__device__ __forceinline__ void ldsm_x4(uint32_t* r, uint32_t a) {
    asm volatile("ldmatrix.sync.aligned.m8n8.x4.shared.b16 {%0,%1,%2,%3}, [%4];"
        : "=r"(r[0]), "=r"(r[1]), "=r"(r[2]), "=r"(r[3]) : "r"(a));
}
__device__ __forceinline__ void ldsm_x4_t(uint32_t* r, uint32_t a) {
    asm volatile("ldmatrix.sync.aligned.m8n8.x4.trans.shared.b16 {%0,%1,%2,%3}, [%4];"
        : "=r"(r[0]), "=r"(r[1]), "=r"(r[2]), "=r"(r[3]) : "r"(a));
}
__device__ __forceinline__ void mma_bf16(float* c, const uint32_t* a, const uint32_t* b) {
    asm volatile("mma.sync.aligned.m16n8k16.row.col.f32.bf16.bf16.f32 "
        "{%0,%1,%2,%3}, {%4,%5,%6,%7}, {%8,%9}, {%0,%1,%2,%3};"
        : "+f"(c[0]), "+f"(c[1]), "+f"(c[2]), "+f"(c[3])
        : "r"(a[0]), "r"(a[1]), "r"(a[2]), "r"(a[3]), "r"(b[0]), "r"(b[1]));
}

// Convert 8 fp32 -> 8 bf16 packed as uint4 (element order preserved).
__device__ __forceinline__ uint4 cvt8h(float4 a, float4 b) {
    float f[8] = {a.x, a.y, a.z, a.w, b.x, b.y, b.z, b.w};
    uint32_t hh[4];
    #pragma unroll
    for (int i = 0; i < 4; i++) {
        __nv_bfloat162 hp;
        hp.x = __float2bfloat16_rn(f[2*i]);
        hp.y = __float2bfloat16_rn(f[2*i+1]);
        hh[i] = *(uint32_t*)&hp;
    }
    return make_uint4(hh[0], hh[1], hh[2], hh[3]);
}

// ---------------------------------------------------------------------------
// conv1x1 core: single-pass bf16 tensor-core MMA.
// Y[b][co][n] = sum_ci W[co][ci] * X[b][ci][n] + bias[co] (+ res)
// XBF: input X is bf16 (else fp32, converted on stage).
// DOBN: accumulate deterministic per-block BN partials (requires fp32 Y + res).
// Block tile 128co x 128n, BK=16, double-buffered SMEM.
// 256 threads = 8 warps in 2(M) x 4(N); warp tile 64co x 32n.
// ---------------------------------------------------------------------------
template<bool XBF, bool DOBN>
__device__ __forceinline__
void conv_core(const float* __restrict__ W, const float* __restrict__ bias,
               const float* __restrict__ Xf, const __nv_bfloat16* __restrict__ Xb,
               const float* __restrict__ res,
               float* __restrict__ Y, __nv_bfloat16* __restrict__ Ybf,
               float* __restrict__ bns1, float* __restrict__ bns2,
               int b, int co0, int n0, int nt)
{
    __shared__ __nv_bfloat16 Wh[2][128 * WS_STRIDE];
    __shared__ __nv_bfloat16 Xh[2][BK * BS_STRIDE];

    const int t    = threadIdx.x;
    const int wid  = t >> 5;
    const int lane = t & 31;

    const int wco = t >> 1;          // 0..127
    const int wk  = (t & 1) * 8;     // 0 or 8
    const int xk  = t >> 4;          // 0..15
    const int xn  = (t & 15) * 8;    // 0..120

    const float* Wr = W + (size_t)(co0 + wco) * Cc + wk;
    const float*         Xrf = XBF ? nullptr : (Xf + ((size_t)b * Cc + xk) * Nn + n0 + xn);
    const __nv_bfloat16* Xrb = XBF ? (Xb + ((size_t)b * Cc + xk) * Nn + n0 + xn) : nullptr;

    const int wm = wid >> 2, wn = wid & 3;
    const int co_w = wm * 64;
    const int n_w  = wn * 32;

    const int lrow = (lane < 16) ? lane : lane - 16;
    const int lho  = (lane < 16) ? 0 : 8;

    float acc[4][4][4];
    #pragma unroll
    for (int mf = 0; mf < 4; mf++)
        #pragma unroll
        for (int nf = 0; nf < 4; nf++)
            #pragma unroll
            for (int r = 0; r < 4; r++) acc[mf][nf][r] = 0.f;

    // ---- stage k-tile 0 ----
    {
        *(uint4*)&Wh[0][wco * WS_STRIDE + wk] =
            cvt8h(*(const float4*)&Wr[0], *(const float4*)&Wr[4]);
        if constexpr (XBF) {
            *(uint4*)&Xh[0][xk * BS_STRIDE + xn] = *(const uint4*)&Xrb[0];
        } else {
            *(uint4*)&Xh[0][xk * BS_STRIDE + xn] =
                cvt8h(*(const float4*)&Xrf[0], *(const float4*)&Xrf[4]);
        }
    }
    __syncthreads();

    int buf = 0;
    for (int k0 = BK; k0 <= Cc; k0 += BK) {
        const bool more = (k0 < Cc);
        float4 wv0, wv1, xv0, xv1;
        uint4 xvb;
        if (more) {
            wv0 = *(const float4*)&Wr[k0];
            wv1 = *(const float4*)&Wr[k0 + 4];
            if constexpr (XBF) {
                xvb = *(const uint4*)&Xrb[(size_t)k0 * Nn];
            } else {
                xv0 = *(const float4*)&Xrf[(size_t)k0 * Nn];
                xv1 = *(const float4*)&Xrf[(size_t)k0 * Nn + 4];
            }
        }

        // ---- single-pass MMA on current buffer ----
        {
            uint32_t Ah[4][4], Bh[4][2];
            #pragma unroll
            for (int mf = 0; mf < 4; mf++)
                ldsm_x4(Ah[mf], sm_u32(&Wh[buf][(co_w + 16 * mf + lrow) * WS_STRIDE + lho]));
            #pragma unroll
            for (int ng = 0; ng < 2; ng++) {
                uint32_t r[4];
                ldsm_x4_t(r, sm_u32(&Xh[buf][lrow * BS_STRIDE + n_w + 16 * ng + lho]));
                Bh[2*ng][0] = r[0]; Bh[2*ng][1] = r[1];
                Bh[2*ng+1][0] = r[2]; Bh[2*ng+1][1] = r[3];
            }
            #pragma unroll
            for (int mf = 0; mf < 4; mf++)
                #pragma unroll
                for (int nf = 0; nf < 4; nf++)
                    mma_bf16(acc[mf][nf], Ah[mf], Bh[nf]);
        }

        if (more) {
            const int nb = buf ^ 1;
            *(uint4*)&Wh[nb][wco * WS_STRIDE + wk] = cvt8h(wv0, wv1);
            if constexpr (XBF) {
                *(uint4*)&Xh[nb][xk * BS_STRIDE + xn] = xvb;
            } else {
                *(uint4*)&Xh[nb][xk * BS_STRIDE + xn] = cvt8h(xv0, xv1);
            }
            __syncthreads();
            buf = nb;
        }
    }

    // ---- epilogue: D frag (c0,c1)=(g,2c..2c+1), (c2,c3)=(g+8,2c..2c+1) ----
    const int g = lane >> 2;
    const int c2c = (lane & 3) * 2;

    float s1[4][2], s2[4][2];
    if constexpr (DOBN) {
        #pragma unroll
        for (int mf = 0; mf < 4; mf++) { s1[mf][0]=0.f; s1[mf][1]=0.f; s2[mf][0]=0.f; s2[mf][1]=0.f; }
    }

    #pragma unroll
    for (int mf = 0; mf < 4; mf++) {
        const int row0 = co0 + co_w + 16 * mf + g;
        const float bv0 = bias[row0];
        const float bv1 = bias[row0 + 8];
        #pragma unroll
        for (int nf = 0; nf < 4; nf++) {
            const int col = n0 + n_w + 8 * nf + c2c;
            const size_t off0 = ((size_t)b * Cc + row0) * Nn + col;
            const size_t off1 = off0 + (size_t)8 * Nn;
            float2 v0 = make_float2(acc[mf][nf][0] + bv0, acc[mf][nf][1] + bv0);
            float2 v1 = make_float2(acc[mf][nf][2] + bv1, acc[mf][nf][3] + bv1);
            if constexpr (DOBN) {
                float2 r0 = *(const float2*)&res[off0];
                float2 r1 = *(const float2*)&res[off1];
                v0.x += r0.x; v0.y += r0.y;
                v1.x += r1.x; v1.y += r1.y;
                *(float2*)&Y[off0] = v0;
                *(float2*)&Y[off1] = v1;
                s1[mf][0] += v0.x + v0.y;
                s2[mf][0] = fmaf(v0.x, v0.x, fmaf(v0.y, v0.y, s2[mf][0]));
                s1[mf][1] += v1.x + v1.y;
                s2[mf][1] = fmaf(v1.x, v1.x, fmaf(v1.y, v1.y, s2[mf][1]));
            } else {
                __nv_bfloat162 p0, p1;
                p0.x = __float2bfloat16_rn(v0.x); p0.y = __float2bfloat16_rn(v0.y);
                p1.x = __float2bfloat16_rn(v1.x); p1.y = __float2bfloat16_rn(v1.y);
                *(__nv_bfloat162*)&Ybf[off0] = p0;
                *(__nv_bfloat162*)&Ybf[off1] = p1;
            }
        }
    }

    if constexpr (DOBN) {
        // reduce over the 4 lanes sharing a row (lane&3 varies col)
        #pragma unroll
        for (int mf = 0; mf < 4; mf++)
            #pragma unroll
            for (int hh = 0; hh < 2; hh++) {
                s1[mf][hh] += __shfl_xor_sync(0xffffffffu, s1[mf][hh], 1);
                s1[mf][hh] += __shfl_xor_sync(0xffffffffu, s1[mf][hh], 2);
                s2[mf][hh] += __shfl_xor_sync(0xffffffffu, s2[mf][hh], 1);
                s2[mf][hh] += __shfl_xor_sync(0xffffffffu, s2[mf][hh], 2);
            }
        __shared__ float bnred[2][128][4];
        if ((lane & 3) == 0) {
            #pragma unroll
            for (int mf = 0; mf < 4; mf++)
                #pragma unroll
                for (int hh = 0; hh < 2; hh++) {
                    const int lrw = co_w + 16 * mf + g + 8 * hh;   // 0..127
                    bnred[0][lrw][wn] = s1[mf][hh];
                    bnred[1][lrw][wn] = s2[mf][hh];
                }
        }
        __syncthreads();
        if (t < 128) {
            float a = 0.f, q = 0.f;
            #pragma unroll
            for (int w = 0; w < 4; w++) { a += bnred[0][t][w]; q += bnred[1][t][w]; }
            const int slot = (co0 + t) * 256 + b * 32 + nt;
            bns1[slot] = a;
            bns2[slot] = q;
        }
    }
}

// Batched q/k/v convs (fp32 in, bf16 out). grid = (32, 2, 48); cid = z%6, b = z/6.
struct QkvBatch {
    const float* W[6];
    const float* bias[6];
    const float* X[6];
    __nv_bfloat16* Y[6];
};

__global__ __launch_bounds__(256, 2)
void conv_qkv_k(QkvBatch cb)
{
    const int z   = blockIdx.z;
    const int cid = z % 6;
    const int b   = z / 6;
    conv_core<false, false>(cb.W[cid], cb.bias[cid], cb.X[cid], nullptr, nullptr,
                            nullptr, cb.Y[cid], nullptr, nullptr,
                            b, blockIdx.y * 128, blockIdx.x * 128, blockIdx.x);
}

// Batched proj convs (bf16 in, fp32 out + residual + BN partials). grid = (32, 2, 16).
struct ProjBatch {
    const float* W[2];
    const float* bias[2];
    const __nv_bfloat16* X[2];
    const float* res[2];
    float* Y[2];
    float* s1[2];
    float* s2[2];
};

__global__ __launch_bounds__(256, 2)
void conv_proj_k(ProjBatch cb)
{
    const int z   = blockIdx.z;
    const int cid = z & 1;
    const int b   = z >> 1;
    conv_core<true, true>(cb.W[cid], cb.bias[cid], nullptr, cb.X[cid], cb.res[cid],
                          cb.Y[cid], nullptr, cb.s1[cid], cb.s2[cid],
                          b, blockIdx.y * 128, blockIdx.x * 128, blockIdx.x);
}

// ---------------------------------------------------------------------------
// Row softmax over N=4096 (bf16 in place, fp32 math), four tensors per launch.
// grid = (B*C, 4), 256 threads, uint4 vectorized (8 bf16 per load).
// ---------------------------------------------------------------------------
struct SmPtrs { __nv_bfloat16* p[4]; };

__global__ __launch_bounds__(256)
void softmax4_k(SmPtrs sp)
{
    __nv_bfloat16* p = sp.p[blockIdx.y] + (size_t)blockIdx.x * Nn;
    uint4* row4 = (uint4*)p;                  // 512 uint4 per row
    const int t = threadIdx.x;

    uint4 ua = row4[t];
    uint4 ub = row4[t + 256];
    float v[16];
    {
        const uint32_t* w = (const uint32_t*)&ua;
        #pragma unroll
        for (int i = 0; i < 4; i++) {
            __nv_bfloat162 h = *(const __nv_bfloat162*)&w[i];
            v[2*i]   = __bfloat162float(h.x);
            v[2*i+1] = __bfloat162float(h.y);
        }
        const uint32_t* w2 = (const uint32_t*)&ub;
        #pragma unroll
        for (int i = 0; i < 4; i++) {
            __nv_bfloat162 h = *(const __nv_bfloat162*)&w2[i];
            v[8+2*i]   = __bfloat162float(h.x);
            v[8+2*i+1] = __bfloat162float(h.y);
        }
    }

    float m = -3.0e38f;
    #pragma unroll
    for (int i = 0; i < 16; i++) m = fmaxf(m, v[i]);

    __shared__ float red[8];
    m = warpMax(m);
    if ((t & 31) == 0) red[t >> 5] = m;
    __syncthreads();
    m = red[0];
    #pragma unroll
    for (int i = 1; i < 8; i++) m = fmaxf(m, red[i]);
    __syncthreads();

    float s = 0.f;
    #pragma unroll
    for (int i = 0; i < 16; i++) { v[i] = __expf(v[i] - m); s += v[i]; }
    s = warpSum(s);
    if ((t & 31) == 0) red[t >> 5] = s;
    __syncthreads();
    s = red[0];
    #pragma unroll
    for (int i = 1; i < 8; i++) s += red[i];

    const float inv = 1.f / s;
    {
        uint32_t* w = (uint32_t*)&ua;
        #pragma unroll
        for (int i = 0; i < 4; i++) {
            __nv_bfloat162 h;
            h.x = __float2bfloat16_rn(v[2*i] * inv);
            h.y = __float2bfloat16_rn(v[2*i+1] * inv);
            w[i] = *(uint32_t*)&h;
        }
        uint32_t* w2 = (uint32_t*)&ub;
        #pragma unroll
        for (int i = 0; i < 4; i++) {
            __nv_bfloat162 h;
            h.x = __float2bfloat16_rn(v[8+2*i] * inv);
            h.y = __float2bfloat16_rn(v[8+2*i+1] * inv);
            w2[i] = *(uint32_t*)&h;
        }
    }
    row4[t] = ua;
    row4[t + 256] = ub;
}

// ---------------------------------------------------------------------------
// ctx partials via MMA: part[chunk][bh2][e][d] = sum_{n in chunk} K[d,n]*V[e,n]
// (stored TRANSPOSED so ctx_reduce reads coalesce)
// A = K tile [d][n] row-major -> non-trans ldmatrix (W pattern).
// B = V tile [e][n] canonical col-major -> non-trans ldmatrix,
//     lane map row=(lane&7)+((lane>>4)<<3), koff=lane&8.
// grid = (NCHUNK, 64); 256 threads; warps 4(M=d16) x 2(N=e32).
// ---------------------------------------------------------------------------
__global__ __launch_bounds__(256)
void ctx_part_k()
{
    const int chunk = blockIdx.x;
    const int bh2 = blockIdx.y;
    const int branch = bh2 >> 5;
    const int bh = bh2 & 31;
    const int b = bh >> 2, h = bh & 3;

    __shared__ __nv_bfloat16 Ks[64 * KS_STRIDE];
    __shared__ __nv_bfloat16 Vs[64 * KS_STRIDE];

    const int t    = threadIdx.x;
    const int wid  = t >> 5;
    const int lane = t & 31;

    const int wm = wid >> 1;         // 0..3 -> d offset wm*16
    const int wn = wid & 1;          // 0..1 -> e offset wn*32

    const int lrow = (lane < 16) ? lane : lane - 16;
    const int lho  = (lane < 16) ? 0 : 8;
    const int brow = (lane & 7) + ((lane >> 4) << 3);
    const int bko  = lane & 8;

    const __nv_bfloat16* Kp = g_kh[branch] + ((size_t)b * Cc + h * HD) * Nn;
    const __nv_bfloat16* Vp = g_vh[branch] + ((size_t)b * Cc + h * HD) * Nn;

    float acc[4][4];
    #pragma unroll
    for (int nf = 0; nf < 4; nf++)
        #pragma unroll
        for (int r = 0; r < 4; r++) acc[nf][r] = 0.f;

    const int srow = t >> 2;          // 0..63
    const int scol = (t & 3) * 8;     // 0, 8, 16, 24
    const int nBeg = chunk * (Nn / NCHUNK);
    const int NIT = (Nn / NCHUNK) / 32;   // 16 iterations

    uint4 kreg = *(const uint4*)&Kp[(size_t)srow * Nn + nBeg + scol];
    uint4 vreg = *(const uint4*)&Vp[(size_t)srow * Nn + nBeg + scol];

    for (int it = 0; it < NIT; it++) {
        __syncthreads();
        *(uint4*)&Ks[srow * KS_STRIDE + scol] = kreg;
        *(uint4*)&Vs[srow * KS_STRIDE + scol] = vreg;
        if (it + 1 < NIT) {
            const int n1 = nBeg + (it + 1) * 32;
            kreg = *(const uint4*)&Kp[(size_t)srow * Nn + n1 + scol];
            vreg = *(const uint4*)&Vp[(size_t)srow * Nn + n1 + scol];
        }
        __syncthreads();

        #pragma unroll
        for (int kk = 0; kk < 2; kk++) {
            uint32_t A[4];
            ldsm_x4(A, sm_u32(&Ks[(wm * 16 + lrow) * KS_STRIDE + kk * 16 + lho]));
            uint32_t Bf[4][2];
            #pragma unroll
            for (int eg = 0; eg < 2; eg++) {
                uint32_t r[4];
                ldsm_x4(r, sm_u32(&Vs[(wn * 32 + eg * 16 + brow) * KS_STRIDE + kk * 16 + bko]));
                Bf[2*eg][0]   = r[0]; Bf[2*eg][1]   = r[1];
                Bf[2*eg+1][0] = r[2]; Bf[2*eg+1][1] = r[3];
            }
            #pragma unroll
            for (int nf = 0; nf < 4; nf++)
                mma_bf16(acc[nf], A, Bf[nf]);
        }
    }

    // transposed store: part[e][d]
    float* outp = g_ctx_part + ((size_t)chunk * 64 + bh2) * (HD * HD);
    const int g = lane >> 2;
    const int cc = (lane & 3) * 2;
    #pragma unroll
    for (int nf = 0; nf < 4; nf++) {
        const int e = wn * 32 + nf * 8 + cc;
        const int d0 = wm * 16 + g;
        outp[e * HD + d0]           = acc[nf][0];
        outp[(e + 1) * HD + d0]     = acc[nf][1];
        outp[e * HD + d0 + 8]       = acc[nf][2];
        outp[(e + 1) * HD + d0 + 8] = acc[nf][3];
    }
}

// Reduce chunks; partials already transposed -> coalesced reads; bf16 out.
__global__ __launch_bounds__(256)
void ctx_reduce_k()
{
    const int idx = blockIdx.x * 256 + threadIdx.x;
    if (idx < 2 * CTXSZ) {
        const int bh2 = idx >> 12;
        const int r = idx & 4095;      // = e*64 + d
        float s = 0.f;
        #pragma unroll
        for (int c = 0; c < NCHUNK; c++)
            s += g_ctx_part[((size_t)c * 64 + bh2) * (HD * HD) + r];
        g_ctxT[idx] = __float2bfloat16_rn(s);
    }
}

// ---------------------------------------------------------------------------
// attn out via MMA: out[e][n] = sum_d ctxT[e][d] * q[d][n]  (bf16 out)
// A = ctxT [e][d] row-major -> non-trans (W pattern). B = q [d][n] -> trans (X pattern).
// grid = (Nn/128, 64); 256 threads; warps 2(M=e32) x 4(N=n32); K=64 (4 iters).
// ---------------------------------------------------------------------------
__global__ __launch_bounds__(256)
void attn_out_k()
{
    const int n0 = blockIdx.x * 128;
    const int bh2 = blockIdx.y;
    const int branch = bh2 >> 5;
    const int bh = bh2 & 31;
    const int b = bh >> 2, h = bh & 3;

    __shared__ __nv_bfloat16 Cs[64 * CS_STRIDE];   // ctxT rows e, cols d
    __shared__ __nv_bfloat16 Qs[64 * BS_STRIDE];   // q rows d, cols n (128)

    const int t    = threadIdx.x;
    const int wid  = t >> 5;
    const int lane = t & 31;

    {
        const __nv_bfloat16* src = g_ctxT + (size_t)bh2 * (HD * HD);
        #pragma unroll
        for (int i = 0; i < 2; i++) {
            const int idx = t + i * 256;
            const int row = idx >> 3;
            const int c8 = (idx & 7) * 8;
            *(uint4*)&Cs[row * CS_STRIDE + c8] = *(const uint4*)&src[row * HD + c8];
        }
    }
    {
        const __nv_bfloat16* src = g_qh[branch] + ((size_t)b * Cc + h * HD) * Nn + n0;
        #pragma unroll
        for (int i = 0; i < 4; i++) {
            const int idx = t + i * 256;
            const int row = idx >> 4;
            const int c8 = (idx & 15) * 8;
            *(uint4*)&Qs[row * BS_STRIDE + c8] = *(const uint4*)&src[(size_t)row * Nn + c8];
        }
    }
    __syncthreads();

    const int wm = wid >> 2;
    const int wn = wid & 3;
    const int lrow = (lane < 16) ? lane : lane - 16;
    const int lho  = (lane < 16) ? 0 : 8;

    float acc[2][4][4];
    #pragma unroll
    for (int mf = 0; mf < 2; mf++)
        #pragma unroll
        for (int nf = 0; nf < 4; nf++)
            #pragma unroll
            for (int r = 0; r < 4; r++) acc[mf][nf][r] = 0.f;

    #pragma unroll
    for (int kk = 0; kk < 4; kk++) {
        uint32_t A[2][4], Bf[4][2];
        #pragma unroll
        for (int mf = 0; mf < 2; mf++)
            ldsm_x4(A[mf], sm_u32(&Cs[(wm * 32 + mf * 16 + lrow) * CS_STRIDE + kk * 16 + lho]));
        #pragma unroll
        for (int ng = 0; ng < 2; ng++) {
            uint32_t r[4];
            ldsm_x4_t(r, sm_u32(&Qs[(kk * 16 + lrow) * BS_STRIDE + wn * 32 + 16 * ng + lho]));
            Bf[2*ng][0]   = r[0]; Bf[2*ng][1]   = r[1];
            Bf[2*ng+1][0] = r[2]; Bf[2*ng+1][1] = r[3];
        }
        #pragma unroll
        for (int mf = 0; mf < 2; mf++)
            #pragma unroll
            for (int nf = 0; nf < 4; nf++)
                mma_bf16(acc[mf][nf], A[mf], Bf[nf]);
    }

    const int g = lane >> 2;
    const int cc = (lane & 3) * 2;
    __nv_bfloat16* outp = g_attnh[branch] + ((size_t)b * Cc + h * HD) * Nn;
    #pragma unroll
    for (int mf = 0; mf < 2; mf++) {
        const int e0 = wm * 32 + mf * 16 + g;
        #pragma unroll
        for (int nf = 0; nf < 4; nf++) {
            const int col = n0 + wn * 32 + nf * 8 + cc;
            __nv_bfloat162 p0, p1;
            p0.x = __float2bfloat16_rn(acc[mf][nf][0]);
            p0.y = __float2bfloat16_rn(acc[mf][nf][1]);
            p1.x = __float2bfloat16_rn(acc[mf][nf][2]);
            p1.y = __float2bfloat16_rn(acc[mf][nf][3]);
            *(__nv_bfloat162*)&outp[(size_t)e0 * Nn + col]       = p0;
            *(__nv_bfloat162*)&outp[(size_t)(e0 + 8) * Nn + col] = p1;
        }
    }
}

// ---------------------------------------------------------------------------
// BN finalize from partials. grid = 512 (branch*256 + c), 256 threads.
// ---------------------------------------------------------------------------
__global__ __launch_bounds__(256)
void bn_finalize_k()
{
    const int ch = blockIdx.x;       // branch*256 + c
    const int t = threadIdx.x;
    float s1 = g_bns1[(size_t)ch * 256 + t];
    float s2 = g_bns2[(size_t)ch * 256 + t];
    __shared__ float r1[8], r2[8];
    s1 = warpSum(s1); s2 = warpSum(s2);
    if ((t & 31) == 0) { r1[t >> 5] = s1; r2[t >> 5] = s2; }
    __syncthreads();
    if (t == 0) {
        float a = 0.f, q = 0.f;
        #pragma unroll
        for (int i = 0; i < 8; i++) { a += r1[i]; q += r2[i]; }
        const float mean = a * (1.f / 32768.f);
        const float var  = q * (1.f / 32768.f) - mean * mean;
        g_mean[ch] = mean;
        g_rstd[ch] = rsqrtf(var + 1e-5f);
    }
}

// BN apply on branches 0/1 of out, PLUS dsm passthrough copies into out[2T..4T).
// grid covers 4*TSIZE/4 uint4 slots: first half BN, second half copy.
__global__ __launch_bounds__(256)
void bn_apply_copy_k(float* __restrict__ Y, const float* __restrict__ gamma,
                     const float* __restrict__ beta,
                     const float* __restrict__ dsm_low,
                     const float* __restrict__ dsm_high)
{
    const size_t idx4 = (size_t)blockIdx.x * 256 + threadIdx.x;
    const size_t bn4  = (size_t)2 * TSIZE / 4;   // uint4 slots for BN
    if (idx4 < bn4) {
        const size_t e = idx4 * 4;
        const int branch = (int)(e / TSIZE);
        const int c = (int)((e / Nn) % Cc);
        const float m = g_mean[branch * Cc + c];
        const float r = g_rstd[branch * Cc + c];
        const float g = gamma[c] * r;
        const float bt = beta[c] - m * g;
        float4 x = ((float4*)Y)[idx4];
        x.x = fmaf(x.x, g, bt);
        x.y = fmaf(x.y, g, bt);
        x.z = fmaf(x.z, g, bt);
        x.w = fmaf(x.w, g, bt);
        ((float4*)Y)[idx4] = x;
    } else {
        const size_t c4 = idx4 - bn4;            // 0 .. 2*TSIZE/4
        const size_t half = (size_t)TSIZE / 4;
        if (c4 < half) {
            ((float4*)Y)[bn4 + c4] = ((const float4*)dsm_low)[c4];
        } else {
            ((float4*)Y)[bn4 + c4] = ((const float4*)dsm_high)[c4 - half];
        }
    }
}

// ---------------------------------------------------------------------------
extern "C" void kernel_launch(void* const* d_in, const int* in_sizes, int n_in,
                              void* d_out, int out_size)
{
    const float* rgb_low  = (const float*)d_in[0];
    const float* rgb_high = (const float*)d_in[1];
    const float* dsm_low  = (const float*)d_in[2];
    const float* dsm_high = (const float*)d_in[3];
    const float* w_q1 = (const float*)d_in[4];   const float* b_q1 = (const float*)d_in[5];
    const float* w_k1 = (const float*)d_in[6];   const float* b_k1 = (const float*)d_in[7];
    const float* w_v1 = (const float*)d_in[8];   const float* b_v1 = (const float*)d_in[9];
    const float* w_q2 = (const float*)d_in[10];  const float* b_q2 = (const float*)d_in[11];
    const float* w_k2 = (const float*)d_in[12];  const float* b_k2 = (const float*)d_in[13];
    const float* w_v2 = (const float*)d_in[14];  const float* b_v2 = (const float*)d_in[15];
    const float* w_p1 = (const float*)d_in[16];  const float* b_p1 = (const float*)d_in[17];
    const float* w_p2 = (const float*)d_in[18];  const float* b_p2 = (const float*)d_in[19];
    const float* gamma = (const float*)d_in[20];
    const float* beta  = (const float*)d_in[21];

    float* out = (float*)d_out;

    __nv_bfloat16 *qh, *kh, *vh, *ah;
    float *bs1, *bs2;
    cudaGetSymbolAddress((void**)&qh,  g_qh);
    cudaGetSymbolAddress((void**)&kh,  g_kh);
    cudaGetSymbolAddress((void**)&vh,  g_vh);
    cudaGetSymbolAddress((void**)&ah,  g_attnh);
    cudaGetSymbolAddress((void**)&bs1, g_bns1);
    cudaGetSymbolAddress((void**)&bs2, g_bns2);

    // ---- All six q/k/v convs (fp32 -> bf16), both branches, one launch ----
    {
        QkvBatch cb;
        cb.W[0] = w_q1; cb.bias[0] = b_q1; cb.X[0] = rgb_low;  cb.Y[0] = qh;
        cb.W[1] = w_k1; cb.bias[1] = b_k1; cb.X[1] = dsm_high; cb.Y[1] = kh;
        cb.W[2] = w_v1; cb.bias[2] = b_v1; cb.X[2] = dsm_high; cb.Y[2] = vh;
        cb.W[3] = w_q2; cb.bias[3] = b_q2; cb.X[3] = rgb_high; cb.Y[3] = qh + TSIZE;
        cb.W[4] = w_k2; cb.bias[4] = b_k2; cb.X[4] = dsm_low;  cb.Y[4] = kh + TSIZE;
        cb.W[5] = w_v2; cb.bias[5] = b_v2; cb.X[5] = dsm_low;  cb.Y[5] = vh + TSIZE;
        conv_qkv_k<<<dim3(Nn / 128, Cc / 128, 6 * Bb), 256>>>(cb);
    }

    // ---- Softmax q1, k1, q2, k2 (bf16 in place) ----
    {
        SmPtrs sp;
        sp.p[0] = qh; sp.p[1] = kh; sp.p[2] = qh + TSIZE; sp.p[3] = kh + TSIZE;
        softmax4_k<<<dim3(Bb * Cc, 4), 256>>>(sp);
    }

    // ---- Attention (MMA, both branches batched) ----
    ctx_part_k<<<dim3(NCHUNK, 64), 256>>>();
    ctx_reduce_k<<<(2 * CTXSZ + 255) / 256, 256>>>();
    attn_out_k<<<dim3(Nn / 128, 64), 256>>>();

    // ---- Both proj convs (bf16 in, fp32 out + residual + BN partials) ----
    {
        ProjBatch cb;
        cb.W[0] = w_p1; cb.bias[0] = b_p1; cb.X[0] = ah;         cb.res[0] = rgb_low;
        cb.Y[0] = out;         cb.s1[0] = bs1;         cb.s2[0] = bs2;
        cb.W[1] = w_p2; cb.bias[1] = b_p2; cb.X[1] = ah + TSIZE; cb.res[1] = rgb_high;
        cb.Y[1] = out + TSIZE; cb.s1[1] = bs1 + 65536; cb.s2[1] = bs2 + 65536;
        conv_proj_k<<<dim3(Nn / 128, Cc / 128, 2 * Bb), 256>>>(cb);
    }

    // ---- BatchNorm + dsm passthrough (fused: 268 MB at full BW) ----
    bn_finalize_k<<<2 * Cc, 256>>>();
    bn_apply_copy_k<<<(4 * TSIZE / 4 + 255) / 256, 256>>>(out, gamma, beta,
                                                          dsm_low, dsm_high);
}

// round 15
// speedup vs baseline: 1.3207x; 1.0111x over previous
#include <cuda_runtime.h>
#include <cuda_bf16.h>
#include <math.h>
#include <stdint.h>

#define Bb 8
#define Cc 256
#define Nn 4096
#define HEADS 4
#define HD 64
#define TSIZE (Bb*Cc*Nn)          // 8,388,608 elems per tensor
#define CTXSZ (Bb*HEADS*HD*HD)    // 131,072 per branch
#define NCHUNK 8

#define BK 16
#define WS_STRIDE 24              // 16 k + 8 pad (bf16) -> 48B rows
#define BS_STRIDE 136             // 128 n + 8 pad (bf16) -> 272B rows
#define CS_STRIDE 72              // 64 d + 8 pad (bf16) -> 144B rows
#define KS_STRIDE 40              // 32 n + 8 pad (bf16) -> 80B rows

// Scratch (device globals: no allocation allowed in kernel_launch).
__device__ __nv_bfloat16  g_qh[2][TSIZE];       // q conv out, then softmaxed (in place)
__device__ __nv_bfloat16  g_kh[2][TSIZE];       // k conv out / softmax; REUSED as proj inter
__device__ __nv_bfloat16  g_vh[2][TSIZE];       // v conv out
__device__ __nv_bfloat16  g_attnh[2][TSIZE];    // attention out (bf16, proj input)
__device__ float          g_ctx_part[NCHUNK * 2 * CTXSZ];  // [chunk][bh2][e][d] (transposed)
__device__ __nv_bfloat16  g_ctxT[2 * CTXSZ];    // [bh2][e][d]
__device__ float          g_bns1[2 * 256 * 256];  // BN partial sums   [branch][c][b*32+nt]
__device__ float          g_bns2[2 * 256 * 256];  // BN partial sumsq
__device__ float          g_mean[2 * Cc];
__device__ float          g_rstd[2 * Cc];

__inline__ __device__ float warpMax(float v) {
    #pragma unroll
    for (int o = 16; o; o >>= 1) v = fmaxf(v, __shfl_xor_sync(0xffffffffu, v, o));
    return v;
}
__inline__ __device__ float warpSum(float v) {
    #pragma unroll
    for (int o = 16; o; o >>= 1) v += __shfl_xor_sync(0xffffffffu, v, o);
    return v;
}

// ---------------------------------------------------------------------------
// MMA helpers
// ---------------------------------------------------------------------------
__device__ __forceinline__ uint32_t sm_u32(const void* p) {
    return (uint32_t)__cvta_generic_to_shared(p);
}
__device__ __forceinline__ void ldsm_x4(uint32_t* r, uint32_t a) {
    asm volatile("ldmatrix.sync.aligned.m8n8.x4.shared.b16 {%0,%1,%2,%3}, [%4];"
        : "=r"(r[0]), "=r"(r[1]), "=r"(r[2]), "=r"(r[3]) : "r"(a));
}
__device__ __forceinline__ void ldsm_x4_t(uint32_t* r, uint32_t a) {
    asm volatile("ldmatrix.sync.aligned.m8n8.x4.trans.shared.b16 {%0,%1,%2,%3}, [%4];"
        : "=r"(r[0]), "=r"(r[1]), "=r"(r[2]), "=r"(r[3]) : "r"(a));
}
__device__ __forceinline__ void mma_bf16(float* c, const uint32_t* a, const uint32_t* b) {
    asm volatile("mma.sync.aligned.m16n8k16.row.col.f32.bf16.bf16.f32 "
        "{%0,%1,%2,%3}, {%4,%5,%6,%7}, {%8,%9}, {%0,%1,%2,%3};"
        : "+f"(c[0]), "+f"(c[1]), "+f"(c[2]), "+f"(c[3])
        : "r"(a[0]), "r"(a[1]), "r"(a[2]), "r"(a[3]), "r"(b[0]), "r"(b[1]));
}

// Convert 8 fp32 -> 8 bf16 packed as uint4 (element order preserved).
__device__ __forceinline__ uint4 cvt8h(float4 a, float4 b) {
    float f[8] = {a.x, a.y, a.z, a.w, b.x, b.y, b.z, b.w};
    uint32_t hh[4];
    #pragma unroll
    for (int i = 0; i < 4; i++) {
        __nv_bfloat162 hp;
        hp.x = __float2bfloat16_rn(f[2*i]);
        hp.y = __float2bfloat16_rn(f[2*i+1]);
        hh[i] = *(uint32_t*)&hp;
    }
    return make_uint4(hh[0], hh[1], hh[2], hh[3]);
}

// ---------------------------------------------------------------------------
// conv1x1 core: single-pass bf16 tensor-core MMA.
// Y = W X + bias. Non-BN path writes bf16 result to Ybf.
// DOBN path: writes bf16 INTER (= WX + bias, no residual) to Ybf, and
// accumulates deterministic per-block BN partials from fp32 y = inter + res.
// Block tile 128co x 128n, BK=16, double-buffered SMEM.
// 256 threads = 8 warps in 2(M) x 4(N); warp tile 64co x 32n.
// ---------------------------------------------------------------------------
template<bool XBF, bool DOBN>
__device__ __forceinline__
void conv_core(const float* __restrict__ W, const float* __restrict__ bias,
               const float* __restrict__ Xf, const __nv_bfloat16* __restrict__ Xb,
               const float* __restrict__ res,
               __nv_bfloat16* __restrict__ Ybf,
               float* __restrict__ bns1, float* __restrict__ bns2,
               int b, int co0, int n0, int nt)
{
    __shared__ __nv_bfloat16 Wh[2][128 * WS_STRIDE];
    __shared__ __nv_bfloat16 Xh[2][BK * BS_STRIDE];

    const int t    = threadIdx.x;
    const int wid  = t >> 5;
    const int lane = t & 31;

    const int wco = t >> 1;          // 0..127
    const int wk  = (t & 1) * 8;     // 0 or 8
    const int xk  = t >> 4;          // 0..15
    const int xn  = (t & 15) * 8;    // 0..120

    const float* Wr = W + (size_t)(co0 + wco) * Cc + wk;
    const float*         Xrf = XBF ? nullptr : (Xf + ((size_t)b * Cc + xk) * Nn + n0 + xn);
    const __nv_bfloat16* Xrb = XBF ? (Xb + ((size_t)b * Cc + xk) * Nn + n0 + xn) : nullptr;

    const int wm = wid >> 2, wn = wid & 3;
    const int co_w = wm * 64;
    const int n_w  = wn * 32;

    const int lrow = (lane < 16) ? lane : lane - 16;
    const int lho  = (lane < 16) ? 0 : 8;

    float acc[4][4][4];
    #pragma unroll
    for (int mf = 0; mf < 4; mf++)
        #pragma unroll
        for (int nf = 0; nf < 4; nf++)
            #pragma unroll
            for (int r = 0; r < 4; r++) acc[mf][nf][r] = 0.f;

    // ---- stage k-tile 0 ----
    {
        *(uint4*)&Wh[0][wco * WS_STRIDE + wk] =
            cvt8h(*(const float4*)&Wr[0], *(const float4*)&Wr[4]);
        if constexpr (XBF) {
            *(uint4*)&Xh[0][xk * BS_STRIDE + xn] = *(const uint4*)&Xrb[0];
        } else {
            *(uint4*)&Xh[0][xk * BS_STRIDE + xn] =
                cvt8h(*(const float4*)&Xrf[0], *(const float4*)&Xrf[4]);
        }
    }
    __syncthreads();

    int buf = 0;
    for (int k0 = BK; k0 <= Cc; k0 += BK) {
        const bool more = (k0 < Cc);
        float4 wv0, wv1, xv0, xv1;
        uint4 xvb;
        if (more) {
            wv0 = *(const float4*)&Wr[k0];
            wv1 = *(const float4*)&Wr[k0 + 4];
            if constexpr (XBF) {
                xvb = *(const uint4*)&Xrb[(size_t)k0 * Nn];
            } else {
                xv0 = *(const float4*)&Xrf[(size_t)k0 * Nn];
                xv1 = *(const float4*)&Xrf[(size_t)k0 * Nn + 4];
            }
        }

        // ---- single-pass MMA on current buffer ----
        {
            uint32_t Ah[4][4], Bh[4][2];
            #pragma unroll
            for (int mf = 0; mf < 4; mf++)
                ldsm_x4(Ah[mf], sm_u32(&Wh[buf][(co_w + 16 * mf + lrow) * WS_STRIDE + lho]));
            #pragma unroll
            for (int ng = 0; ng < 2; ng++) {
                uint32_t r[4];
                ldsm_x4_t(r, sm_u32(&Xh[buf][lrow * BS_STRIDE + n_w + 16 * ng + lho]));
                Bh[2*ng][0] = r[0]; Bh[2*ng][1] = r[1];
                Bh[2*ng+1][0] = r[2]; Bh[2*ng+1][1] = r[3];
            }
            #pragma unroll
            for (int mf = 0; mf < 4; mf++)
                #pragma unroll
                for (int nf = 0; nf < 4; nf++)
                    mma_bf16(acc[mf][nf], Ah[mf], Bh[nf]);
        }

        if (more) {
            const int nb = buf ^ 1;
            *(uint4*)&Wh[nb][wco * WS_STRIDE + wk] = cvt8h(wv0, wv1);
            if constexpr (XBF) {
                *(uint4*)&Xh[nb][xk * BS_STRIDE + xn] = xvb;
            } else {
                *(uint4*)&Xh[nb][xk * BS_STRIDE + xn] = cvt8h(xv0, xv1);
            }
            __syncthreads();
            buf = nb;
        }
    }

    // ---- epilogue: D frag (c0,c1)=(g,2c..2c+1), (c2,c3)=(g+8,2c..2c+1) ----
    const int g = lane >> 2;
    const int c2c = (lane & 3) * 2;

    float s1[4][2], s2[4][2];
    if constexpr (DOBN) {
        #pragma unroll
        for (int mf = 0; mf < 4; mf++) { s1[mf][0]=0.f; s1[mf][1]=0.f; s2[mf][0]=0.f; s2[mf][1]=0.f; }
    }

    #pragma unroll
    for (int mf = 0; mf < 4; mf++) {
        const int row0 = co0 + co_w + 16 * mf + g;
        const float bv0 = bias[row0];
        const float bv1 = bias[row0 + 8];
        #pragma unroll
        for (int nf = 0; nf < 4; nf++) {
            const int col = n0 + n_w + 8 * nf + c2c;
            const size_t off0 = ((size_t)b * Cc + row0) * Nn + col;
            const size_t off1 = off0 + (size_t)8 * Nn;
            float2 v0 = make_float2(acc[mf][nf][0] + bv0, acc[mf][nf][1] + bv0);
            float2 v1 = make_float2(acc[mf][nf][2] + bv1, acc[mf][nf][3] + bv1);
            // store bf16 result (inter for DOBN; full result otherwise)
            __nv_bfloat162 p0, p1;
            p0.x = __float2bfloat16_rn(v0.x); p0.y = __float2bfloat16_rn(v0.y);
            p1.x = __float2bfloat16_rn(v1.x); p1.y = __float2bfloat16_rn(v1.y);
            *(__nv_bfloat162*)&Ybf[off0] = p0;
            *(__nv_bfloat162*)&Ybf[off1] = p1;
            if constexpr (DOBN) {
                float2 r0 = *(const float2*)&res[off0];
                float2 r1 = *(const float2*)&res[off1];
                const float y00 = v0.x + r0.x, y01 = v0.y + r0.y;
                const float y10 = v1.x + r1.x, y11 = v1.y + r1.y;
                s1[mf][0] += y00 + y01;
                s2[mf][0] = fmaf(y00, y00, fmaf(y01, y01, s2[mf][0]));
                s1[mf][1] += y10 + y11;
                s2[mf][1] = fmaf(y10, y10, fmaf(y11, y11, s2[mf][1]));
            }
        }
    }

    if constexpr (DOBN) {
        // reduce over the 4 lanes sharing a row (lane&3 varies col)
        #pragma unroll
        for (int mf = 0; mf < 4; mf++)
            #pragma unroll
            for (int hh = 0; hh < 2; hh++) {
                s1[mf][hh] += __shfl_xor_sync(0xffffffffu, s1[mf][hh], 1);
                s1[mf][hh] += __shfl_xor_sync(0xffffffffu, s1[mf][hh], 2);
                s2[mf][hh] += __shfl_xor_sync(0xffffffffu, s2[mf][hh], 1);
                s2[mf][hh] += __shfl_xor_sync(0xffffffffu, s2[mf][hh], 2);
            }
        __shared__ float bnred[2][128][4];
        if ((lane & 3) == 0) {
            #pragma unroll
            for (int mf = 0; mf < 4; mf++)
                #pragma unroll
                for (int hh = 0; hh < 2; hh++) {
                    const int lrw = co_w + 16 * mf + g + 8 * hh;   // 0..127
                    bnred[0][lrw][wn] = s1[mf][hh];
                    bnred[1][lrw][wn] = s2[mf][hh];
                }
        }
        __syncthreads();
        if (t < 128) {
            float a = 0.f, q = 0.f;
            #pragma unroll
            for (int w = 0; w < 4; w++) { a += bnred[0][t][w]; q += bnred[1][t][w]; }
            const int slot = (co0 + t) * 256 + b * 32 + nt;
            bns1[slot] = a;
            bns2[slot] = q;
        }
    }
}

// Batched q/k/v convs (fp32 in, bf16 out). grid = (32, 2, 48); cid = z%6, b = z/6.
struct QkvBatch {
    const float* W[6];
    const float* bias[6];
    const float* X[6];
    __nv_bfloat16* Y[6];
};

__global__ __launch_bounds__(256, 2)
void conv_qkv_k(QkvBatch cb)
{
    const int z   = blockIdx.z;
    const int cid = z % 6;
    const int b   = z / 6;
    conv_core<false, false>(cb.W[cid], cb.bias[cid], cb.X[cid], nullptr, nullptr,
                            cb.Y[cid], nullptr, nullptr,
                            b, blockIdx.y * 128, blockIdx.x * 128, blockIdx.x);
}

// Batched proj convs (bf16 in, bf16 INTER out + BN partials from inter+res).
// grid = (32, 2, 16).
struct ProjBatch {
    const float* W[2];
    const float* bias[2];
    const __nv_bfloat16* X[2];
    const float* res[2];
    __nv_bfloat16* Yb[2];
    float* s1[2];
    float* s2[2];
};

__global__ __launch_bounds__(256, 2)
void conv_proj_k(ProjBatch cb)
{
    const int z   = blockIdx.z;
    const int cid = z & 1;
    const int b   = z >> 1;
    conv_core<true, true>(cb.W[cid], cb.bias[cid], nullptr, cb.X[cid], cb.res[cid],
                          cb.Yb[cid], cb.s1[cid], cb.s2[cid],
                          b, blockIdx.y * 128, blockIdx.x * 128, blockIdx.x);
}

// ---------------------------------------------------------------------------
// Row softmax over N=4096 (bf16 in place, fp32 math), four tensors per launch.
// grid = (B*C, 4), 256 threads, uint4 vectorized (8 bf16 per load).
// ---------------------------------------------------------------------------
struct SmPtrs { __nv_bfloat16* p[4]; };

__global__ __launch_bounds__(256)
void softmax4_k(SmPtrs sp)
{
    __nv_bfloat16* p = sp.p[blockIdx.y] + (size_t)blockIdx.x * Nn;
    uint4* row4 = (uint4*)p;                  // 512 uint4 per row
    const int t = threadIdx.x;

    uint4 ua = row4[t];
    uint4 ub = row4[t + 256];
    float v[16];
    {
        const uint32_t* w = (const uint32_t*)&ua;
        #pragma unroll
        for (int i = 0; i < 4; i++) {
            __nv_bfloat162 h = *(const __nv_bfloat162*)&w[i];
            v[2*i]   = __bfloat162float(h.x);
            v[2*i+1] = __bfloat162float(h.y);
        }
        const uint32_t* w2 = (const uint32_t*)&ub;
        #pragma unroll
        for (int i = 0; i < 4; i++) {
            __nv_bfloat162 h = *(const __nv_bfloat162*)&w2[i];
            v[8+2*i]   = __bfloat162float(h.x);
            v[8+2*i+1] = __bfloat162float(h.y);
        }
    }

    float m = -3.0e38f;
    #pragma unroll
    for (int i = 0; i < 16; i++) m = fmaxf(m, v[i]);

    __shared__ float red[8];
    m = warpMax(m);
    if ((t & 31) == 0) red[t >> 5] = m;
    __syncthreads();
    m = red[0];
    #pragma unroll
    for (int i = 1; i < 8; i++) m = fmaxf(m, red[i]);
    __syncthreads();

    float s = 0.f;
    #pragma unroll
    for (int i = 0; i < 16; i++) { v[i] = __expf(v[i] - m); s += v[i]; }
    s = warpSum(s);
    if ((t & 31) == 0) red[t >> 5] = s;
    __syncthreads();
    s = red[0];
    #pragma unroll
    for (int i = 1; i < 8; i++) s += red[i];

    const float inv = 1.f / s;
    {
        uint32_t* w = (uint32_t*)&ua;
        #pragma unroll
        for (int i = 0; i < 4; i++) {
            __nv_bfloat162 h;
            h.x = __float2bfloat16_rn(v[2*i] * inv);
            h.y = __float2bfloat16_rn(v[2*i+1] * inv);
            w[i] = *(uint32_t*)&h;
        }
        uint32_t* w2 = (uint32_t*)&ub;
        #pragma unroll
        for (int i = 0; i < 4; i++) {
            __nv_bfloat162 h;
            h.x = __float2bfloat16_rn(v[8+2*i] * inv);
            h.y = __float2bfloat16_rn(v[8+2*i+1] * inv);
            w2[i] = *(uint32_t*)&h;
        }
    }
    row4[t] = ua;
    row4[t + 256] = ub;
}

// ---------------------------------------------------------------------------
// ctx partials via MMA: part[chunk][bh2][e][d] = sum_{n in chunk} K[d,n]*V[e,n]
// (stored TRANSPOSED so ctx_reduce reads coalesce)
// grid = (NCHUNK, 64); 256 threads; warps 4(M=d16) x 2(N=e32).
// ---------------------------------------------------------------------------
__global__ __launch_bounds__(256)
void ctx_part_k()
{
    const int chunk = blockIdx.x;
    const int bh2 = blockIdx.y;
    const int branch = bh2 >> 5;
    const int bh = bh2 & 31;
    const int b = bh >> 2, h = bh & 3;

    __shared__ __nv_bfloat16 Ks[64 * KS_STRIDE];
    __shared__ __nv_bfloat16 Vs[64 * KS_STRIDE];

    const int t    = threadIdx.x;
    const int wid  = t >> 5;
    const int lane = t & 31;

    const int wm = wid >> 1;         // 0..3 -> d offset wm*16
    const int wn = wid & 1;          // 0..1 -> e offset wn*32

    const int lrow = (lane < 16) ? lane : lane - 16;
    const int lho  = (lane < 16) ? 0 : 8;
    const int brow = (lane & 7) + ((lane >> 4) << 3);
    const int bko  = lane & 8;

    const __nv_bfloat16* Kp = g_kh[branch] + ((size_t)b * Cc + h * HD) * Nn;
    const __nv_bfloat16* Vp = g_vh[branch] + ((size_t)b * Cc + h * HD) * Nn;

    float acc[4][4];
    #pragma unroll
    for (int nf = 0; nf < 4; nf++)
        #pragma unroll
        for (int r = 0; r < 4; r++) acc[nf][r] = 0.f;

    const int srow = t >> 2;          // 0..63
    const int scol = (t & 3) * 8;     // 0, 8, 16, 24
    const int nBeg = chunk * (Nn / NCHUNK);
    const int NIT = (Nn / NCHUNK) / 32;   // 16 iterations

    uint4 kreg = *(const uint4*)&Kp[(size_t)srow * Nn + nBeg + scol];
    uint4 vreg = *(const uint4*)&Vp[(size_t)srow * Nn + nBeg + scol];

    for (int it = 0; it < NIT; it++) {
        __syncthreads();
        *(uint4*)&Ks[srow * KS_STRIDE + scol] = kreg;
        *(uint4*)&Vs[srow * KS_STRIDE + scol] = vreg;
        if (it + 1 < NIT) {
            const int n1 = nBeg + (it + 1) * 32;
            kreg = *(const uint4*)&Kp[(size_t)srow * Nn + n1 + scol];
            vreg = *(const uint4*)&Vp[(size_t)srow * Nn + n1 + scol];
        }
        __syncthreads();

        #pragma unroll
        for (int kk = 0; kk < 2; kk++) {
            uint32_t A[4];
            ldsm_x4(A, sm_u32(&Ks[(wm * 16 + lrow) * KS_STRIDE + kk * 16 + lho]));
            uint32_t Bf[4][2];
            #pragma unroll
            for (int eg = 0; eg < 2; eg++) {
                uint32_t r[4];
                ldsm_x4(r, sm_u32(&Vs[(wn * 32 + eg * 16 + brow) * KS_STRIDE + kk * 16 + bko]));
                Bf[2*eg][0]   = r[0]; Bf[2*eg][1]   = r[1];
                Bf[2*eg+1][0] = r[2]; Bf[2*eg+1][1] = r[3];
            }
            #pragma unroll
            for (int nf = 0; nf < 4; nf++)
                mma_bf16(acc[nf], A, Bf[nf]);
        }
    }

    // transposed store: part[e][d]
    float* outp = g_ctx_part + ((size_t)chunk * 64 + bh2) * (HD * HD);
    const int g = lane >> 2;
    const int cc = (lane & 3) * 2;
    #pragma unroll
    for (int nf = 0; nf < 4; nf++) {
        const int e = wn * 32 + nf * 8 + cc;
        const int d0 = wm * 16 + g;
        outp[e * HD + d0]           = acc[nf][0];
        outp[(e + 1) * HD + d0]     = acc[nf][1];
        outp[e * HD + d0 + 8]       = acc[nf][2];
        outp[(e + 1) * HD + d0 + 8] = acc[nf][3];
    }
}

// Reduce chunks; partials already transposed -> coalesced reads; bf16 out.
__global__ __launch_bounds__(256)
void ctx_reduce_k()
{
    const int idx = blockIdx.x * 256 + threadIdx.x;
    if (idx < 2 * CTXSZ) {
        const int bh2 = idx >> 12;
        const int r = idx & 4095;      // = e*64 + d
        float s = 0.f;
        #pragma unroll
        for (int c = 0; c < NCHUNK; c++)
            s += g_ctx_part[((size_t)c * 64 + bh2) * (HD * HD) + r];
        g_ctxT[idx] = __float2bfloat16_rn(s);
    }
}

// ---------------------------------------------------------------------------
// attn out via MMA: out[e][n] = sum_d ctxT[e][d] * q[d][n]  (bf16 out)
// grid = (Nn/128, 64); 256 threads; warps 2(M=e32) x 4(N=n32); K=64 (4 iters).
// ---------------------------------------------------------------------------
__global__ __launch_bounds__(256)
void attn_out_k()
{
    const int n0 = blockIdx.x * 128;
    const int bh2 = blockIdx.y;
    const int branch = bh2 >> 5;
    const int bh = bh2 & 31;
    const int b = bh >> 2, h = bh & 3;

    __shared__ __nv_bfloat16 Cs[64 * CS_STRIDE];   // ctxT rows e, cols d
    __shared__ __nv_bfloat16 Qs[64 * BS_STRIDE];   // q rows d, cols n (128)

    const int t    = threadIdx.x;
    const int wid  = t >> 5;
    const int lane = t & 31;

    {
        const __nv_bfloat16* src = g_ctxT + (size_t)bh2 * (HD * HD);
        #pragma unroll
        for (int i = 0; i < 2; i++) {
            const int idx = t + i * 256;
            const int row = idx >> 3;
            const int c8 = (idx & 7) * 8;
            *(uint4*)&Cs[row * CS_STRIDE + c8] = *(const uint4*)&src[row * HD + c8];
        }
    }
    {
        const __nv_bfloat16* src = g_qh[branch] + ((size_t)b * Cc + h * HD) * Nn + n0;
        #pragma unroll
        for (int i = 0; i < 4; i++) {
            const int idx = t + i * 256;
            const int row = idx >> 4;
            const int c8 = (idx & 15) * 8;
            *(uint4*)&Qs[row * BS_STRIDE + c8] = *(const uint4*)&src[(size_t)row * Nn + c8];
        }
    }
    __syncthreads();

    const int wm = wid >> 2;
    const int wn = wid & 3;
    const int lrow = (lane < 16) ? lane : lane - 16;
    const int lho  = (lane < 16) ? 0 : 8;

    float acc[2][4][4];
    #pragma unroll
    for (int mf = 0; mf < 2; mf++)
        #pragma unroll
        for (int nf = 0; nf < 4; nf++)
            #pragma unroll
            for (int r = 0; r < 4; r++) acc[mf][nf][r] = 0.f;

    #pragma unroll
    for (int kk = 0; kk < 4; kk++) {
        uint32_t A[2][4], Bf[4][2];
        #pragma unroll
        for (int mf = 0; mf < 2; mf++)
            ldsm_x4(A[mf], sm_u32(&Cs[(wm * 32 + mf * 16 + lrow) * CS_STRIDE + kk * 16 + lho]));
        #pragma unroll
        for (int ng = 0; ng < 2; ng++) {
            uint32_t r[4];
            ldsm_x4_t(r, sm_u32(&Qs[(kk * 16 + lrow) * BS_STRIDE + wn * 32 + 16 * ng + lho]));
            Bf[2*ng][0]   = r[0]; Bf[2*ng][1]   = r[1];
            Bf[2*ng+1][0] = r[2]; Bf[2*ng+1][1] = r[3];
        }
        #pragma unroll
        for (int mf = 0; mf < 2; mf++)
            #pragma unroll
            for (int nf = 0; nf < 4; nf++)
                mma_bf16(acc[mf][nf], A[mf], Bf[nf]);
    }

    const int g = lane >> 2;
    const int cc = (lane & 3) * 2;
    __nv_bfloat16* outp = g_attnh[branch] + ((size_t)b * Cc + h * HD) * Nn;
    #pragma unroll
    for (int mf = 0; mf < 2; mf++) {
        const int e0 = wm * 32 + mf * 16 + g;
        #pragma unroll
        for (int nf = 0; nf < 4; nf++) {
            const int col = n0 + wn * 32 + nf * 8 + cc;
            __nv_bfloat162 p0, p1;
            p0.x = __float2bfloat16_rn(acc[mf][nf][0]);
            p0.y = __float2bfloat16_rn(acc[mf][nf][1]);
            p1.x = __float2bfloat16_rn(acc[mf][nf][2]);
            p1.y = __float2bfloat16_rn(acc[mf][nf][3]);
            *(__nv_bfloat162*)&outp[(size_t)e0 * Nn + col]       = p0;
            *(__nv_bfloat162*)&outp[(size_t)(e0 + 8) * Nn + col] = p1;
        }
    }
}

// ---------------------------------------------------------------------------
// BN finalize from partials. grid = 512 (branch*256 + c), 256 threads.
// ---------------------------------------------------------------------------
__global__ __launch_bounds__(256)
void bn_finalize_k()
{
    const int ch = blockIdx.x;       // branch*256 + c
    const int t = threadIdx.x;
    float s1 = g_bns1[(size_t)ch * 256 + t];
    float s2 = g_bns2[(size_t)ch * 256 + t];
    __shared__ float r1[8], r2[8];
    s1 = warpSum(s1); s2 = warpSum(s2);
    if ((t & 31) == 0) { r1[t >> 5] = s1; r2[t >> 5] = s2; }
    __syncthreads();
    if (t == 0) {
        float a = 0.f, q = 0.f;
        #pragma unroll
        for (int i = 0; i < 8; i++) { a += r1[i]; q += r2[i]; }
        const float mean = a * (1.f / 32768.f);
        const float var  = q * (1.f / 32768.f) - mean * mean;
        g_mean[ch] = mean;
        g_rstd[ch] = rsqrtf(var + 1e-5f);
    }
}

// BN apply: y = bf16_inter + rgb, normalized -> out[0..2T).
// Plus dsm passthrough copies into out[2T..4T). 8 elems per thread.
__global__ __launch_bounds__(256)
void bn_apply_copy_k(float* __restrict__ Y, const float* __restrict__ gamma,
                     const float* __restrict__ beta,
                     const __nv_bfloat16* __restrict__ inter,   // [2][TSIZE]
                     const float* __restrict__ rgb_low,
                     const float* __restrict__ rgb_high,
                     const float* __restrict__ dsm_low,
                     const float* __restrict__ dsm_high)
{
    const size_t idx8 = (size_t)blockIdx.x * 256 + threadIdx.x;
    const size_t bn8  = (size_t)2 * TSIZE / 8;   // 8-elem slots for BN
    if (idx8 < bn8) {
        const size_t e = idx8 * 8;
        const int branch = (int)(e / TSIZE);
        const size_t le = e - (size_t)branch * TSIZE;
        const int c = (int)((le / Nn) % Cc);
        const float m = g_mean[branch * Cc + c];
        const float r = g_rstd[branch * Cc + c];
        const float g = gamma[c] * r;
        const float bt = beta[c] - m * g;
        const float* res = branch ? rgb_high : rgb_low;

        uint4 iv = *(const uint4*)&inter[e];
        float4 r0 = *(const float4*)&res[le];
        float4 r1 = *(const float4*)&res[le + 4];
        const uint32_t* w = (const uint32_t*)&iv;
        float f[8];
        #pragma unroll
        for (int i = 0; i < 4; i++) {
            __nv_bfloat162 h = *(const __nv_bfloat162*)&w[i];
            f[2*i]   = __bfloat162float(h.x);
            f[2*i+1] = __bfloat162float(h.y);
        }
        float4 o0, o1;
        o0.x = fmaf(f[0] + r0.x, g, bt);
        o0.y = fmaf(f[1] + r0.y, g, bt);
        o0.z = fmaf(f[2] + r0.z, g, bt);
        o0.w = fmaf(f[3] + r0.w, g, bt);
        o1.x = fmaf(f[4] + r1.x, g, bt);
        o1.y = fmaf(f[5] + r1.y, g, bt);
        o1.z = fmaf(f[6] + r1.z, g, bt);
        o1.w = fmaf(f[7] + r1.w, g, bt);
        *(float4*)&Y[e]     = o0;
        *(float4*)&Y[e + 4] = o1;
    } else {
        const size_t c8 = idx8 - bn8;            // 0 .. 2*TSIZE/8
        const size_t half8 = (size_t)TSIZE / 8;
        const size_t dstE = (size_t)2 * TSIZE + c8 * 8;
        if (c8 < half8) {
            const size_t se = c8 * 8;
            *(float4*)&Y[dstE]     = *(const float4*)&dsm_low[se];
            *(float4*)&Y[dstE + 4] = *(const float4*)&dsm_low[se + 4];
        } else {
            const size_t se = (c8 - half8) * 8;
            *(float4*)&Y[dstE]     = *(const float4*)&dsm_high[se];
            *(float4*)&Y[dstE + 4] = *(const float4*)&dsm_high[se + 4];
        }
    }
}

// ---------------------------------------------------------------------------
extern "C" void kernel_launch(void* const* d_in, const int* in_sizes, int n_in,
                              void* d_out, int out_size)
{
    const float* rgb_low  = (const float*)d_in[0];
    const float* rgb_high = (const float*)d_in[1];
    const float* dsm_low  = (const float*)d_in[2];
    const float* dsm_high = (const float*)d_in[3];
    const float* w_q1 = (const float*)d_in[4];   const float* b_q1 = (const float*)d_in[5];
    const float* w_k1 = (const float*)d_in[6];   const float* b_k1 = (const float*)d_in[7];
    const float* w_v1 = (const float*)d_in[8];   const float* b_v1 = (const float*)d_in[9];
    const float* w_q2 = (const float*)d_in[10];  const float* b_q2 = (const float*)d_in[11];
    const float* w_k2 = (const float*)d_in[12];  const float* b_k2 = (const float*)d_in[13];
    const float* w_v2 = (const float*)d_in[14];  const float* b_v2 = (const float*)d_in[15];
    const float* w_p1 = (const float*)d_in[16];  const float* b_p1 = (const float*)d_in[17];
    const float* w_p2 = (const float*)d_in[18];  const float* b_p2 = (const float*)d_in[19];
    const float* gamma = (const float*)d_in[20];
    const float* beta  = (const float*)d_in[21];

    float* out = (float*)d_out;

    __nv_bfloat16 *qh, *kh, *vh, *ah;
    float *bs1, *bs2;
    cudaGetSymbolAddress((void**)&qh,  g_qh);
    cudaGetSymbolAddress((void**)&kh,  g_kh);
    cudaGetSymbolAddress((void**)&vh,  g_vh);
    cudaGetSymbolAddress((void**)&ah,  g_attnh);
    cudaGetSymbolAddress((void**)&bs1, g_bns1);
    cudaGetSymbolAddress((void**)&bs2, g_bns2);

    // ---- All six q/k/v convs (fp32 -> bf16), both branches, one launch ----
    {
        QkvBatch cb;
        cb.W[0] = w_q1; cb.bias[0] = b_q1; cb.X[0] = rgb_low;  cb.Y[0] = qh;
        cb.W[1] = w_k1; cb.bias[1] = b_k1; cb.X[1] = dsm_high; cb.Y[1] = kh;
        cb.W[2] = w_v1; cb.bias[2] = b_v1; cb.X[2] = dsm_high; cb.Y[2] = vh;
        cb.W[3] = w_q2; cb.bias[3] = b_q2; cb.X[3] = rgb_high; cb.Y[3] = qh + TSIZE;
        cb.W[4] = w_k2; cb.bias[4] = b_k2; cb.X[4] = dsm_low;  cb.Y[4] = kh + TSIZE;
        cb.W[5] = w_v2; cb.bias[5] = b_v2; cb.X[5] = dsm_low;  cb.Y[5] = vh + TSIZE;
        conv_qkv_k<<<dim3(Nn / 128, Cc / 128, 6 * Bb), 256>>>(cb);
    }

    // ---- Softmax q1, k1, q2, k2 (bf16 in place) ----
    {
        SmPtrs sp;
        sp.p[0] = qh; sp.p[1] = kh; sp.p[2] = qh + TSIZE; sp.p[3] = kh + TSIZE;
        softmax4_k<<<dim3(Bb * Cc, 4), 256>>>(sp);
    }

    // ---- Attention (MMA, both branches batched) ----
    ctx_part_k<<<dim3(NCHUNK, 64), 256>>>();      // consumes kh, vh
    ctx_reduce_k<<<(2 * CTXSZ + 255) / 256, 256>>>();
    attn_out_k<<<dim3(Nn / 128, 64), 256>>>();    // consumes qh, writes ah

    // ---- Both proj convs: bf16 inter -> kh (dead after ctx_part) + BN partials ----
    {
        ProjBatch cb;
        cb.W[0] = w_p1; cb.bias[0] = b_p1; cb.X[0] = ah;         cb.res[0] = rgb_low;
        cb.Yb[0] = kh;          cb.s1[0] = bs1;         cb.s2[0] = bs2;
        cb.W[1] = w_p2; cb.bias[1] = b_p2; cb.X[1] = ah + TSIZE; cb.res[1] = rgb_high;
        cb.Yb[1] = kh + TSIZE;  cb.s1[1] = bs1 + 65536; cb.s2[1] = bs2 + 65536;
        conv_proj_k<<<dim3(Nn / 128, Cc / 128, 2 * Bb), 256>>>(cb);
    }

    // ---- BatchNorm apply (recompute y = inter + rgb) + dsm passthrough ----
    bn_finalize_k<<<2 * Cc, 256>>>();
    bn_apply_copy_k<<<(4 * TSIZE / 8 + 255) / 256, 256>>>(out, gamma, beta,
                                                          kh, rgb_low, rgb_high,
                                                          dsm_low, dsm_high);
}